// round 10
// baseline (speedup 1.0000x reference)
#include <cuda_runtime.h>
#include <cuda_bf16.h>
#include <cstdint>

#define BB 8
#define CC 64
#define OO 64
#define HH 96
#define WW 96
#define HW (HH*WW)
#define K2 9
#define NOFF 18
#define WP 100              // padded width/height
#define XTB (WP*WP*CC)      // padded per-batch xt size

typedef unsigned long long ull;
typedef unsigned short ushort_t;

#define PACKF2(d, lo, hi) asm("mov.b64 %0, {%1,%2};" : "=l"(d) : "f"(lo), "f"(hi))
#define UNPKF2(lo, hi, s) asm("mov.b64 {%0,%1}, %2;" : "=f"(lo), "=f"(hi) : "l"(s))
#define FMA2(d, a, b, c)  asm("fma.rn.f32x2 %0, %1, %2, %3;" : "=l"(d) : "l"(a), "l"(b), "l"(c))

__device__ __forceinline__ uint32_t smem_u32(const void* p) {
    uint32_t a;
    asm("{ .reg .u64 t; cvta.to.shared.u64 t, %1; cvt.u32.u64 %0, t; }" : "=r"(a) : "l"(p));
    return a;
}

#define LDSM_X4(r0, r1, r2, r3, addr) \
    asm volatile("ldmatrix.sync.aligned.m8n8.x4.shared.b16 {%0,%1,%2,%3}, [%4];" \
                 : "=r"(r0), "=r"(r1), "=r"(r2), "=r"(r3) : "r"(addr))

#define MMA16816(ac, a0, a1, a2, a3, b0, b1) \
    asm volatile("mma.sync.aligned.m16n8k16.row.col.f32.bf16.bf16.f32 " \
                 "{%0,%1,%2,%3}, {%4,%5,%6,%7}, {%8,%9}, {%0,%1,%2,%3};" \
                 : "+f"((ac)[0]), "+f"((ac)[1]), "+f"((ac)[2]), "+f"((ac)[3]) \
                 : "r"(a0), "r"(a1), "r"(a2), "r"(a3), "r"(b0), "r"(b1))

#define CP_ASYNC16(dst, src) \
    asm volatile("cp.async.cg.shared.global [%0], [%1], 16;" :: "r"(dst), "l"(src))
#define CP_COMMIT() asm volatile("cp.async.commit_group;")
#define CP_WAIT0()  asm volatile("cp.async.wait_group 0;")

// ---------------- scratch -----------------------------------------------------
__device__ float g_xt[BB * XTB];               // padded NHWC x (zero border)
__device__ int    g_pidx[BB * K2 * HW];        // clamped base idx (premul by 64)
__device__ float4 g_pw[BB * K2 * HW];          // masked bilinear weights
__device__ float  g_owt[CC * K2 * 20];
__device__ ushort_t g_bst[K2 * 2 * OO * 72];   // conv_w bf16 [tap][hi/lo][o][72]

// ---------------- transpose NCHW -> padded NHWC --------------------------------
__global__ void transpose_x_kernel(const float* __restrict__ x, float* __restrict__ xt) {
    __shared__ float tile[32][33];
    int blk = blockIdx.x;
    int pt = blk % 288, ct = (blk / 288) & 1, b = blk / 576;
    int lx = threadIdx.x & 31, ly = threadIdx.x >> 5;
    int p0 = pt * 32, c0 = ct * 32;
    int h = p0 / WW, w0 = p0 - h * WW;
    const float* xb = x + (size_t)(b * CC + c0) * HW + p0;
#pragma unroll
    for (int i = 0; i < 4; i++) {
        int cc = ly + 8 * i;
        tile[cc][lx] = xb[(size_t)cc * HW + lx];
    }
    __syncthreads();
    float* xo = xt + (size_t)b * XTB + ((size_t)(h + 2) * WP + (w0 + 2)) * CC + c0;
#pragma unroll
    for (int i = 0; i < 4; i++) {
        int pp = ly + 8 * i;
        xo[(size_t)pp * CC + lx] = tile[lx][pp];
    }
}

// ---------------- weight prep ---------------------------------------------------
__global__ void build_weights_kernel(const float* __restrict__ cw,
                                     const float* __restrict__ ow,
                                     ushort_t* __restrict__ bst,
                                     float* __restrict__ owt) {
    int idx = blockIdx.x * 256 + threadIdx.x;
    if (idx < K2 * OO * CC) {
        int k = idx / (OO * CC);
        int r = idx % (OO * CC);
        int o = r / CC;
        int c = r % CC;
        float v = cw[(size_t)(o * CC + c) * K2 + k];
        __nv_bfloat16 h = __float2bfloat16(v);
        __nv_bfloat16 l = __float2bfloat16(v - __bfloat162float(h));
        bst[((size_t)(k * 2 + 0) * OO + o) * 72 + c] = *(ushort_t*)&h;
        bst[((size_t)(k * 2 + 1) * OO + o) * 72 + c] = *(ushort_t*)&l;
    }
    if (idx < NOFF * CC * K2) {
        int j = idx / (CC * K2);
        int r = idx % (CC * K2);
        int c = r / K2;
        int k = r % K2;
        owt[(c * K2 + k) * 20 + j] = ow[idx];
    }
}

// ---------------- offset conv + position/weight precompute ---------------------
__global__ void __launch_bounds__(256) offset_conv_kernel(
    const float* __restrict__ x, const float* __restrict__ owt,
    const float* __restrict__ ob, int* __restrict__ pidx, float4* __restrict__ pw)
{
    __shared__ float ws[CC * K2 * 20];
    __shared__ float bs[NOFF];
    int tid = threadIdx.x;
    for (int i = tid; i < CC * K2 * 20; i += 256) ws[i] = owt[i];
    if (tid < NOFF) bs[tid] = ob[tid];
    __syncthreads();

    int flat = blockIdx.x * 256 + tid;
    int b = flat / HW, p = flat % HW;
    int h = p / WW, w = p % WW;
    const float* x0 = x + (size_t)b * CC * HW;

    ull a0[9];
#pragma unroll
    for (int j = 0; j < 9; j++) a0[j] = 0ull;

    int yy[3], xx[3]; bool vy[3], vx[3];
#pragma unroll
    for (int d = 0; d < 3; d++) {
        yy[d] = h + d - 1; vy[d] = (unsigned)yy[d] < (unsigned)HH;
        xx[d] = w + d - 1; vx[d] = (unsigned)xx[d] < (unsigned)WW;
    }
    for (int c = 0; c < CC; c++) {
        float xv[9];
        const float* xc = x0 + (size_t)c * HW;
#pragma unroll
        for (int dy = 0; dy < 3; dy++)
#pragma unroll
            for (int dx = 0; dx < 3; dx++) {
                int i = dy * 3 + dx;
                xv[i] = (vy[dy] && vx[dx]) ? xc[yy[dy] * WW + xx[dx]] : 0.f;
            }
#pragma unroll
        for (int i = 0; i < 9; i++) {
            const float* row = ws + (c * K2 + i) * 20;
            ull s0;
            PACKF2(s0, xv[i], xv[i]);
#pragma unroll
            for (int j = 0; j < 9; j++) {
                ull wv = *(const ull*)(row + 2 * j);
                FMA2(a0[j], s0, wv, a0[j]);
            }
        }
    }
#pragma unroll
    for (int t = 0; t < 9; t++) {
        float dy, dx;
        UNPKF2(dy, dx, a0[t]);
        dy += bs[2 * t];
        dx += bs[2 * t + 1];
        float py = (float)(h - 1 + t / 3) + dy;
        float qx = (float)(w - 1 + t % 3) + dx;
        float fy = floorf(py), fx = floorf(qx);
        int y0 = (int)fy, x0i = (int)fx;
        float wy = py - fy, wx = qx - fx;
        bool vy0 = (unsigned)y0 < (unsigned)HH;
        bool vy1 = (unsigned)(y0 + 1) < (unsigned)HH;
        bool vx0 = (unsigned)x0i < (unsigned)WW;
        bool vx1 = (unsigned)(x0i + 1) < (unsigned)WW;
        float w00 = (vy0 && vx0) ? (1.f - wy) * (1.f - wx) : 0.f;
        float w01 = (vy0 && vx1) ? (1.f - wy) * wx         : 0.f;
        float w10 = (vy1 && vx0) ? wy * (1.f - wx)         : 0.f;
        float w11 = (vy1 && vx1) ? wy * wx                 : 0.f;
        int yc = min(max(y0, -2), 95);
        int xc = min(max(x0i, -2), 95);
        size_t gp = ((size_t)(b * 9 + t)) * HW + p;
        pidx[gp] = ((yc + 2) * WP + (xc + 2)) * CC;
        pw[gp]   = make_float4(w00, w01, w10, w11);
    }
}

// ---------------- fused: single-buffer, cp.async B, batched gathers -------------
// 256 thr, tile 128 px x 64 out, 3 CTAs/SM.
#define SM_A 0
#define A_SPLIT 18432            // bytes per A split (128*144)
#define SM_B 36864
#define B_SPLIT 9216
#define SM_TOT (SM_B + 2 * B_SPLIT)   // 55296

__global__ void __launch_bounds__(256, 3)
fused_mma_kernel(const float* __restrict__ xt, const int* __restrict__ pidx,
                 const float4* __restrict__ pw, const ushort_t* __restrict__ bst,
                 const float* __restrict__ cb, float* __restrict__ out)
{
    extern __shared__ char smc[];
    uint32_t sbase = smem_u32(smc);
    int tid = threadIdx.x, wid = tid >> 5, lane = tid & 31;
    int b  = blockIdx.x / 72;
    int p0 = (blockIdx.x % 72) * 128;

    const float* xt_b = xt + (size_t)b * XTB;
    int c2 = 2 * lane;

    float acc[8][4];
#pragma unroll
    for (int i = 0; i < 8; i++)
#pragma unroll
        for (int j = 0; j < 4; j++) acc[i][j] = 0.f;

    int lr = lane & 7;
    uint32_t aoff = (uint32_t)((lr + ((lane >> 3) & 1) * 8) * 144 + (lane >> 4) * 16);
    uint32_t boff = (uint32_t)((lr + (lane >> 4) * 8) * 144 + ((lane >> 3) & 1) * 16);
    uint32_t aH_w = sbase + SM_A + (uint32_t)(wid * 16 * 144) + aoff;
    uint32_t bH_w = sbase + SM_B + boff;

    for (int k = 0; k < 9; k++) {
        // ---- stage B(k) via cp.async (overlaps fill below) ----
        {
            const uint4* src = (const uint4*)(bst + (size_t)k * 9216);
            uint32_t dst = sbase + SM_B;
            for (int i = tid; i < 1152; i += 256)
                CP_ASYNC16(dst + (uint32_t)i * 16, (const void*)(src + i));
            CP_COMMIT();
        }
        // ---- fill A(k): batched idx/w4 loads (MLP 8), then gathers ----
        {
            const int*    pi = pidx + ((size_t)(b * 9 + k)) * HW + p0;
            const float4* pv = pw   + ((size_t)(b * 9 + k)) * HW + p0;
#pragma unroll
            for (int g = 0; g < 2; g++) {
                int    idxv[8];
                float4 wv[8];
#pragma unroll
                for (int j = 0; j < 8; j++) {
                    int px = wid + 8 * (8 * g + j);
                    idxv[j] = __ldg(pi + px);
                    wv[j]   = __ldg(pv + px);
                }
#pragma unroll
                for (int j = 0; j < 8; j++) {
                    int px = wid + 8 * (8 * g + j);
                    const float* base = xt_b + idxv[j] + c2;
                    float2 g00 = *(const float2*)(base);
                    float2 g01 = *(const float2*)(base + CC);
                    float2 g10 = *(const float2*)(base + WP * CC);
                    float2 g11 = *(const float2*)(base + WP * CC + CC);
                    float4 w4 = wv[j];
                    float sx = g00.x*w4.x + g01.x*w4.y + g10.x*w4.z + g11.x*w4.w;
                    float sy = g00.y*w4.x + g01.y*w4.y + g10.y*w4.z + g11.y*w4.w;
                    uint32_t hp, lp;
                    asm("cvt.rn.bf16x2.f32 %0, %1, %2;" : "=r"(hp) : "f"(sy), "f"(sx));
                    float hx = __uint_as_float(hp << 16);
                    float hy = __uint_as_float(hp & 0xffff0000u);
                    asm("cvt.rn.bf16x2.f32 %0, %1, %2;" : "=r"(lp) : "f"(sy - hy), "f"(sx - hx));
                    uint32_t ao = (uint32_t)(px * 144 + lane * 4);
                    *(uint32_t*)(smc + SM_A + ao)           = hp;
                    *(uint32_t*)(smc + SM_A + A_SPLIT + ao) = lp;
                }
            }
        }
        CP_WAIT0();
        __syncthreads();

        // ---- MMA(k): 3 split passes sharing fragments ----
        uint32_t aH = aH_w;
        uint32_t aL = aH + A_SPLIT;
        uint32_t bH = bH_w;
        uint32_t bL = bH + B_SPLIT;
#pragma unroll
        for (int ks = 0; ks < 4; ks++) {
            uint32_t ah0, ah1, ah2, ah3, al0, al1, al2, al3;
            LDSM_X4(ah0, ah1, ah2, ah3, aH + ks * 32);
            LDSM_X4(al0, al1, al2, al3, aL + ks * 32);
            uint32_t bh[4][4];
#pragma unroll
            for (int q = 0; q < 4; q++)
                LDSM_X4(bh[q][0], bh[q][1], bh[q][2], bh[q][3],
                        bH + (uint32_t)(q * 2304) + ks * 32);
#pragma unroll
            for (int nt = 0; nt < 8; nt++) {
                uint32_t* bq = bh[nt >> 1];
                int e = (nt & 1) * 2;
                MMA16816(acc[nt], ah0, ah1, ah2, ah3, bq[e], bq[e + 1]);
            }
#pragma unroll
            for (int nt = 0; nt < 8; nt++) {
                uint32_t* bq = bh[nt >> 1];
                int e = (nt & 1) * 2;
                MMA16816(acc[nt], al0, al1, al2, al3, bq[e], bq[e + 1]);
            }
            uint32_t bl[4][4];
#pragma unroll
            for (int q = 0; q < 4; q++)
                LDSM_X4(bl[q][0], bl[q][1], bl[q][2], bl[q][3],
                        bL + (uint32_t)(q * 2304) + ks * 32);
#pragma unroll
            for (int nt = 0; nt < 8; nt++) {
                uint32_t* bq = bl[nt >> 1];
                int e = (nt & 1) * 2;
                MMA16816(acc[nt], ah0, ah1, ah2, ah3, bq[e], bq[e + 1]);
            }
        }
        __syncthreads();
    }

    // ---- epilogue ----
    int px0 = p0 + wid * 16 + (lane >> 2);
    int ob0 = 2 * (lane & 3);
    float* outb = out + (size_t)b * OO * HW;
#pragma unroll
    for (int nt = 0; nt < 8; nt++) {
        int o = nt * 8 + ob0;
        float b0 = cb[o], b1 = cb[o + 1];
        outb[(size_t)o * HW + px0]           = acc[nt][0] + b0;
        outb[(size_t)(o + 1) * HW + px0]     = acc[nt][1] + b1;
        outb[(size_t)o * HW + px0 + 8]       = acc[nt][2] + b0;
        outb[(size_t)(o + 1) * HW + px0 + 8] = acc[nt][3] + b1;
    }
}

// ---------------- launch ---------------------------------------------------------
extern "C" void kernel_launch(void* const* d_in, const int* in_sizes, int n_in,
                              void* d_out, int out_size) {
    const float* x  = (const float*)d_in[0];
    const float* ow = (const float*)d_in[1];
    const float* ob = (const float*)d_in[2];
    const float* cw = (const float*)d_in[3];
    const float* cb = (const float*)d_in[4];
    float* out = (float*)d_out;

    float *xt, *owt;
    int* pidx;
    float4* pw;
    ushort_t* bst;
    cudaGetSymbolAddress((void**)&xt,   g_xt);
    cudaGetSymbolAddress((void**)&owt,  g_owt);
    cudaGetSymbolAddress((void**)&pidx, g_pidx);
    cudaGetSymbolAddress((void**)&pw,   g_pw);
    cudaGetSymbolAddress((void**)&bst,  g_bst);

    cudaFuncSetAttribute(fused_mma_kernel,
                         cudaFuncAttributeMaxDynamicSharedMemorySize, SM_TOT);

    transpose_x_kernel<<<4608, 256>>>(x, xt);
    build_weights_kernel<<<144, 256>>>(cw, ow, bst, owt);
    offset_conv_kernel<<<288, 256>>>(x, owt, ob, pidx, pw);
    fused_mma_kernel<<<576, 256, SM_TOT>>>(xt, pidx, pw, bst, cb, out);
}

// round 11
// speedup vs baseline: 1.0749x; 1.0749x over previous
#include <cuda_runtime.h>
#include <cuda_bf16.h>
#include <cstdint>

#define BB 8
#define CC 64
#define OO 64
#define HH 96
#define WW 96
#define HW (HH*WW)
#define K2 9
#define NOFF 18
#define WP 100              // padded width/height
#define XTB (WP*WP*CC)

typedef unsigned long long ull;
typedef unsigned short ushort_t;

#define PACKF2(d, lo, hi) asm("mov.b64 %0, {%1,%2};" : "=l"(d) : "f"(lo), "f"(hi))
#define UNPKF2(lo, hi, s) asm("mov.b64 {%0,%1}, %2;" : "=f"(lo), "=f"(hi) : "l"(s))
#define FMA2(d, a, b, c)  asm("fma.rn.f32x2 %0, %1, %2, %3;" : "=l"(d) : "l"(a), "l"(b), "l"(c))
#define SW128(off) ((off) ^ (((off) >> 3) & 0x70))

__device__ __forceinline__ uint32_t smem_u32(const void* p) {
    uint32_t a;
    asm("{ .reg .u64 t; cvta.to.shared.u64 t, %1; cvt.u32.u64 %0, t; }" : "=r"(a) : "l"(p));
    return a;
}

#define LDSM_X4(r0, r1, r2, r3, addr) \
    asm volatile("ldmatrix.sync.aligned.m8n8.x4.shared.b16 {%0,%1,%2,%3}, [%4];" \
                 : "=r"(r0), "=r"(r1), "=r"(r2), "=r"(r3) : "r"(addr))

#define MMA16816(ac, a0, a1, a2, a3, b0, b1) \
    asm volatile("mma.sync.aligned.m16n8k16.row.col.f32.bf16.bf16.f32 " \
                 "{%0,%1,%2,%3}, {%4,%5,%6,%7}, {%8,%9}, {%0,%1,%2,%3};" \
                 : "+f"((ac)[0]), "+f"((ac)[1]), "+f"((ac)[2]), "+f"((ac)[3]) \
                 : "r"(a0), "r"(a1), "r"(a2), "r"(a3), "r"(b0), "r"(b1))

#define CP_ASYNC16(dst, src) \
    asm volatile("cp.async.cg.shared.global [%0], [%1], 16;" :: "r"(dst), "l"(src))
#define CP_COMMIT() asm volatile("cp.async.commit_group;")
#define CP_WAIT0()  asm volatile("cp.async.wait_group 0;")

// ---------------- scratch -----------------------------------------------------
__device__ float   g_xt[BB * XTB];             // padded NHWC x (zero border)
__device__ int     g_pidx[BB * K2 * HW];       // base idx (0 => zero corner if far)
__device__ float2  g_pw2[BB * K2 * HW];        // raw fractions (wy, wx)
__device__ float   g_owt[CC * K2 * 20];
__device__ ushort_t g_bst[K2 * 2 * 4096];      // conv_w bf16 [tap][hi/lo], SW128-swizzled 64x64

// ---------------- transpose NCHW -> padded NHWC --------------------------------
__global__ void transpose_x_kernel(const float* __restrict__ x, float* __restrict__ xt) {
    __shared__ float tile[32][33];
    int blk = blockIdx.x;
    int pt = blk % 288, ct = (blk / 288) & 1, b = blk / 576;
    int lx = threadIdx.x & 31, ly = threadIdx.x >> 5;
    int p0 = pt * 32, c0 = ct * 32;
    int h = p0 / WW, w0 = p0 - h * WW;
    const float* xb = x + (size_t)(b * CC + c0) * HW + p0;
#pragma unroll
    for (int i = 0; i < 4; i++) {
        int cc = ly + 8 * i;
        tile[cc][lx] = xb[(size_t)cc * HW + lx];
    }
    __syncthreads();
    float* xo = xt + (size_t)b * XTB + ((size_t)(h + 2) * WP + (w0 + 2)) * CC + c0;
#pragma unroll
    for (int i = 0; i < 4; i++) {
        int pp = ly + 8 * i;
        xo[(size_t)pp * CC + lx] = tile[lx][pp];
    }
}

// ---------------- weight prep (B pre-swizzled) ----------------------------------
__global__ void build_weights_kernel(const float* __restrict__ cw,
                                     const float* __restrict__ ow,
                                     ushort_t* __restrict__ bst,
                                     float* __restrict__ owt) {
    int idx = blockIdx.x * 256 + threadIdx.x;
    if (idx < K2 * OO * CC) {
        int k = idx / (OO * CC);
        int r = idx % (OO * CC);
        int o = r / CC;
        int c = r % CC;
        float v = cw[(size_t)(o * CC + c) * K2 + k];
        __nv_bfloat16 h = __float2bfloat16(v);
        __nv_bfloat16 l = __float2bfloat16(v - __bfloat162float(h));
        uint32_t sw = SW128((uint32_t)(o * 128 + c * 2)) >> 1;
        bst[(k * 2 + 0) * 4096 + sw] = *(ushort_t*)&h;
        bst[(k * 2 + 1) * 4096 + sw] = *(ushort_t*)&l;
    }
    if (idx < NOFF * CC * K2) {
        int j = idx / (CC * K2);
        int r = idx % (CC * K2);
        int c = r / K2;
        int k = r % K2;
        owt[(c * K2 + k) * 20 + j] = ow[idx];
    }
}

// ---------------- offset conv + position precompute -----------------------------
__global__ void __launch_bounds__(256) offset_conv_kernel(
    const float* __restrict__ x, const float* __restrict__ owt,
    const float* __restrict__ ob, int* __restrict__ pidx, float2* __restrict__ pw2)
{
    __shared__ float ws[CC * K2 * 20];
    __shared__ float bs[NOFF];
    int tid = threadIdx.x;
    for (int i = tid; i < CC * K2 * 20; i += 256) ws[i] = owt[i];
    if (tid < NOFF) bs[tid] = ob[tid];
    __syncthreads();

    int flat = blockIdx.x * 256 + tid;
    int b = flat / HW, p = flat % HW;
    int h = p / WW, w = p % WW;
    const float* x0 = x + (size_t)b * CC * HW;

    ull a0[9];
#pragma unroll
    for (int j = 0; j < 9; j++) a0[j] = 0ull;

    int yy[3], xx[3]; bool vy[3], vx[3];
#pragma unroll
    for (int d = 0; d < 3; d++) {
        yy[d] = h + d - 1; vy[d] = (unsigned)yy[d] < (unsigned)HH;
        xx[d] = w + d - 1; vx[d] = (unsigned)xx[d] < (unsigned)WW;
    }
    for (int c = 0; c < CC; c++) {
        float xv[9];
        const float* xc = x0 + (size_t)c * HW;
#pragma unroll
        for (int dy = 0; dy < 3; dy++)
#pragma unroll
            for (int dx = 0; dx < 3; dx++) {
                int i = dy * 3 + dx;
                xv[i] = (vy[dy] && vx[dx]) ? xc[yy[dy] * WW + xx[dx]] : 0.f;
            }
#pragma unroll
        for (int i = 0; i < 9; i++) {
            const float* row = ws + (c * K2 + i) * 20;
            ull s0;
            PACKF2(s0, xv[i], xv[i]);
#pragma unroll
            for (int j = 0; j < 9; j++) {
                ull wv = *(const ull*)(row + 2 * j);
                FMA2(a0[j], s0, wv, a0[j]);
            }
        }
    }
#pragma unroll
    for (int t = 0; t < 9; t++) {
        float dy, dx;
        UNPKF2(dy, dx, a0[t]);
        dy += bs[2 * t];
        dx += bs[2 * t + 1];
        float py = (float)(h - 1 + t / 3) + dy;
        float qx = (float)(w - 1 + t % 3) + dx;
        float fy = floorf(py), fx = floorf(qx);
        int y0 = (int)fy, x0i = (int)fx;
        float wy = py - fy, wx = qx - fx;
        // zero-border trick: in-range [-2,96] reads reproduce masks exactly;
        // fully-far samples -> idx 0 (pad corner, all-zero reads)
        bool far = (y0 < -2) | (y0 > 96) | (x0i < -2) | (x0i > 96);
        int idx = far ? 0 : ((y0 + 2) * WP + (x0i + 2)) * CC;
        size_t gp = ((size_t)(b * 9 + t)) * HW + p;
        pidx[gp] = idx;
        pw2[gp]  = make_float2(wy, wx);
    }
}

// ---------------- fused: smem idx, SW128 A/B, cp.async B, HMMA ------------------
// 256 thr, tile 128 px x 64 out, 2 CTAs/SM.
// smem map (bytes): A: 4 x 16384 (buf0 hi, buf0 lo, buf1 hi, buf1 lo)
//                   B at 65536: 4 x 8192 (buf0 hi, buf0 lo, buf1 hi, buf1 lo)
//                   sIdx at 98304 (1152 int), sFrac at 102912 (1152 float2)
#define SM_B    65536
#define SM_IDX  98304
#define SM_FR   102912
#define SM_TOT  112128

__global__ void __launch_bounds__(256, 2)
fused_mma_kernel(const float* __restrict__ xt, const int* __restrict__ pidx,
                 const float2* __restrict__ pw2, const ushort_t* __restrict__ bst,
                 const float* __restrict__ cb, float* __restrict__ out)
{
    extern __shared__ char smc[];
    uint32_t sbase = smem_u32(smc);
    int tid = threadIdx.x, wid = tid >> 5, lane = tid & 31;
    int b  = blockIdx.x / 72;
    int p0 = (blockIdx.x % 72) * 128;

    const float* xt_b = xt + (size_t)b * XTB;
    int c2 = 2 * lane;
    int*    sIdx = (int*)(smc + SM_IDX);
    float2* sFr  = (float2*)(smc + SM_FR);

    float acc[8][4];
#pragma unroll
    for (int i = 0; i < 8; i++)
#pragma unroll
        for (int j = 0; j < 4; j++) acc[i][j] = 0.f;

    int lr = lane & 7;
    uint32_t la0 = (uint32_t)((wid * 16 + lr + ((lane >> 3) & 1) * 8) * 128 + (lane >> 4) * 16);
    uint32_t lb0 = (uint32_t)((lr + (lane >> 4) * 8) * 128 + ((lane >> 3) & 1) * 16);

    auto stageB = [&](int k, int buf) {
        const char* src = (const char*)(bst) + (size_t)k * 16384;
        uint32_t dst = sbase + SM_B + (uint32_t)buf * 16384;
#pragma unroll
        for (int i = 0; i < 4; i++) {
            int e = tid + 256 * i;
            CP_ASYNC16(dst + (uint32_t)e * 16, src + (size_t)e * 16);
        }
        CP_COMMIT();
    };
    auto fill = [&](int k, int buf) {
        const int*    si = sIdx + (k << 7);
        const float2* sf = sFr  + (k << 7);
        char* Ab = smc + buf * 32768;
#pragma unroll 4
        for (int j = 0; j < 16; j++) {
            int px = wid + 8 * j;
            int idx = si[px];
            float2 fr = sf[px];
            const float* base = xt_b + idx + c2;
            float2 g00 = *(const float2*)(base);
            float2 g01 = *(const float2*)(base + CC);
            float2 g10 = *(const float2*)(base + WP * CC);
            float2 g11 = *(const float2*)(base + WP * CC + CC);
            float wy = fr.x, wx = fr.y;
            float w00 = (1.f - wy) * (1.f - wx);
            float w01 = (1.f - wy) * wx;
            float w10 = wy * (1.f - wx);
            float w11 = wy * wx;
            float sx = g00.x*w00 + g01.x*w01 + g10.x*w10 + g11.x*w11;
            float sy = g00.y*w00 + g01.y*w01 + g10.y*w10 + g11.y*w11;
            uint32_t hp, lp;
            asm("cvt.rn.bf16x2.f32 %0, %1, %2;" : "=r"(hp) : "f"(sy), "f"(sx));
            float hx = __uint_as_float(hp << 16);
            float hy = __uint_as_float(hp & 0xffff0000u);
            asm("cvt.rn.bf16x2.f32 %0, %1, %2;" : "=r"(lp) : "f"(sy - hy), "f"(sx - hx));
            uint32_t off = (uint32_t)(px * 128 + lane * 4);
            uint32_t sw = SW128(off);
            *(uint32_t*)(Ab + sw)         = hp;
            *(uint32_t*)(Ab + 16384 + sw) = lp;
        }
    };

    // ---- prologue: preload idx/frac for all 9 taps, stage B0, fill A0 ----
    {
        size_t gb = (size_t)(b * 9) * HW + p0;
        for (int i = tid; i < 1152; i += 256) {
            int t = i >> 7, px = i & 127;
            size_t g = gb + (size_t)t * HW + px;
            sIdx[i] = pidx[g];
            sFr[i]  = pw2[g];
        }
    }
    stageB(0, 0);
    __syncthreads();           // idx/frac visible
    fill(0, 0);
    CP_WAIT0();
    __syncthreads();           // A0 + B0 ready

    for (int k = 0; k < 9; k++) {
        int buf = k & 1;
        if (k < 8) stageB(k + 1, buf ^ 1);   // async, overlaps MMA

        // ---- MMA(k) ----
        uint32_t Abase = sbase + (uint32_t)buf * 32768;
        uint32_t Bbase = sbase + SM_B + (uint32_t)buf * 16384;
#pragma unroll
        for (int ks = 0; ks < 4; ks++) {
            uint32_t la = SW128(la0 + ks * 32);
            uint32_t ah0, ah1, ah2, ah3, al0, al1, al2, al3;
            LDSM_X4(ah0, ah1, ah2, ah3, Abase + la);
            LDSM_X4(al0, al1, al2, al3, Abase + la + 16384);
            uint32_t bh[4][4];
#pragma unroll
            for (int q = 0; q < 4; q++) {
                uint32_t lb = SW128(lb0 + (uint32_t)(q * 2048) + ks * 32);
                LDSM_X4(bh[q][0], bh[q][1], bh[q][2], bh[q][3], Bbase + lb);
            }
#pragma unroll
            for (int nt = 0; nt < 8; nt++) {
                uint32_t* bq = bh[nt >> 1];
                int e = (nt & 1) * 2;
                MMA16816(acc[nt], ah0, ah1, ah2, ah3, bq[e], bq[e + 1]);
            }
#pragma unroll
            for (int nt = 0; nt < 8; nt++) {
                uint32_t* bq = bh[nt >> 1];
                int e = (nt & 1) * 2;
                MMA16816(acc[nt], al0, al1, al2, al3, bq[e], bq[e + 1]);
            }
            uint32_t bl[4][4];
#pragma unroll
            for (int q = 0; q < 4; q++) {
                uint32_t lb = SW128(lb0 + (uint32_t)(q * 2048) + ks * 32);
                LDSM_X4(bl[q][0], bl[q][1], bl[q][2], bl[q][3], Bbase + 8192 + lb);
            }
#pragma unroll
            for (int nt = 0; nt < 8; nt++) {
                uint32_t* bq = bl[nt >> 1];
                int e = (nt & 1) * 2;
                MMA16816(acc[nt], ah0, ah1, ah2, ah3, bq[e], bq[e + 1]);
            }
        }

        if (k < 8) {
            fill(k + 1, buf ^ 1);    // gathers overlap tail + other CTA's MMA
            CP_WAIT0();
        }
        __syncthreads();
    }

    // ---- epilogue ----
    int px0 = p0 + wid * 16 + (lane >> 2);
    int ob0 = 2 * (lane & 3);
    float* outb = out + (size_t)b * OO * HW;
#pragma unroll
    for (int nt = 0; nt < 8; nt++) {
        int o = nt * 8 + ob0;
        float b0 = cb[o], b1 = cb[o + 1];
        outb[(size_t)o * HW + px0]           = acc[nt][0] + b0;
        outb[(size_t)(o + 1) * HW + px0]     = acc[nt][1] + b1;
        outb[(size_t)o * HW + px0 + 8]       = acc[nt][2] + b0;
        outb[(size_t)(o + 1) * HW + px0 + 8] = acc[nt][3] + b1;
    }
}

// ---------------- launch ---------------------------------------------------------
extern "C" void kernel_launch(void* const* d_in, const int* in_sizes, int n_in,
                              void* d_out, int out_size) {
    const float* x  = (const float*)d_in[0];
    const float* ow = (const float*)d_in[1];
    const float* ob = (const float*)d_in[2];
    const float* cw = (const float*)d_in[3];
    const float* cb = (const float*)d_in[4];
    float* out = (float*)d_out;

    float *xt, *owt;
    int* pidx;
    float2* pw2;
    ushort_t* bst;
    cudaGetSymbolAddress((void**)&xt,   g_xt);
    cudaGetSymbolAddress((void**)&owt,  g_owt);
    cudaGetSymbolAddress((void**)&pidx, g_pidx);
    cudaGetSymbolAddress((void**)&pw2,  g_pw2);
    cudaGetSymbolAddress((void**)&bst,  g_bst);

    cudaFuncSetAttribute(fused_mma_kernel,
                         cudaFuncAttributeMaxDynamicSharedMemorySize, SM_TOT);

    transpose_x_kernel<<<4608, 256>>>(x, xt);
    build_weights_kernel<<<144, 256>>>(cw, ow, bst, owt);
    offset_conv_kernel<<<288, 256>>>(x, owt, ob, pidx, pw2);
    fused_mma_kernel<<<576, 256, SM_TOT>>>(xt, pidx, pw2, bst, cb, out);
}

// round 12
// speedup vs baseline: 1.1677x; 1.0864x over previous
#include <cuda_runtime.h>
#include <cuda_bf16.h>
#include <cstdint>

#define BB 8
#define CC 64
#define OO 64
#define HH 96
#define WW 96
#define HW (HH*WW)
#define K2 9
#define NOFF 18
#define WP 100              // padded width/height
#define XTB (WP*WP*CC)

typedef unsigned long long ull;
typedef unsigned short ushort_t;

#define PACKF2(d, lo, hi) asm("mov.b64 %0, {%1,%2};" : "=l"(d) : "f"(lo), "f"(hi))
#define UNPKF2(lo, hi, s) asm("mov.b64 {%0,%1}, %2;" : "=f"(lo), "=f"(hi) : "l"(s))
#define FMA2(d, a, b, c)  asm("fma.rn.f32x2 %0, %1, %2, %3;" : "=l"(d) : "l"(a), "l"(b), "l"(c))
#define SW128(off) ((off) ^ (((off) >> 3) & 0x70))

__device__ __forceinline__ uint32_t smem_u32(const void* p) {
    uint32_t a;
    asm("{ .reg .u64 t; cvta.to.shared.u64 t, %1; cvt.u32.u64 %0, t; }" : "=r"(a) : "l"(p));
    return a;
}

#define LDSM_X4(r0, r1, r2, r3, addr) \
    asm volatile("ldmatrix.sync.aligned.m8n8.x4.shared.b16 {%0,%1,%2,%3}, [%4];" \
                 : "=r"(r0), "=r"(r1), "=r"(r2), "=r"(r3) : "r"(addr))

#define MMA16816(ac, a0, a1, a2, a3, b0, b1) \
    asm volatile("mma.sync.aligned.m16n8k16.row.col.f32.bf16.bf16.f32 " \
                 "{%0,%1,%2,%3}, {%4,%5,%6,%7}, {%8,%9}, {%0,%1,%2,%3};" \
                 : "+f"((ac)[0]), "+f"((ac)[1]), "+f"((ac)[2]), "+f"((ac)[3]) \
                 : "r"(a0), "r"(a1), "r"(a2), "r"(a3), "r"(b0), "r"(b1))

#define CP_ASYNC16(dst, src) \
    asm volatile("cp.async.cg.shared.global [%0], [%1], 16;" :: "r"(dst), "l"(src))
#define CP_COMMIT() asm volatile("cp.async.commit_group;")
#define CP_WAIT0()  asm volatile("cp.async.wait_group 0;")

// ---------------- scratch -----------------------------------------------------
__device__ float   g_xt[BB * XTB];             // padded NHWC x (zero border)
__device__ int     g_pidx[BB * K2 * HW];       // base idx (0 => zero corner if far)
__device__ float2  g_pw2[BB * K2 * HW];        // raw fractions (wy, wx)
__device__ float   g_owt[CC * K2 * 20];
__device__ ushort_t g_bst[K2 * 2 * 4096];      // conv_w bf16 [tap][hi/lo], SW128-swizzled

// ---------------- transpose NCHW -> padded NHWC --------------------------------
__global__ void transpose_x_kernel(const float* __restrict__ x, float* __restrict__ xt) {
    __shared__ float tile[32][33];
    int blk = blockIdx.x;
    int pt = blk % 288, ct = (blk / 288) & 1, b = blk / 576;
    int lx = threadIdx.x & 31, ly = threadIdx.x >> 5;
    int p0 = pt * 32, c0 = ct * 32;
    int h = p0 / WW, w0 = p0 - h * WW;
    const float* xb = x + (size_t)(b * CC + c0) * HW + p0;
#pragma unroll
    for (int i = 0; i < 4; i++) {
        int cc = ly + 8 * i;
        tile[cc][lx] = xb[(size_t)cc * HW + lx];
    }
    __syncthreads();
    float* xo = xt + (size_t)b * XTB + ((size_t)(h + 2) * WP + (w0 + 2)) * CC + c0;
#pragma unroll
    for (int i = 0; i < 4; i++) {
        int pp = ly + 8 * i;
        xo[(size_t)pp * CC + lx] = tile[lx][pp];
    }
}

// ---------------- weight prep (B pre-swizzled) ----------------------------------
__global__ void build_weights_kernel(const float* __restrict__ cw,
                                     const float* __restrict__ ow,
                                     ushort_t* __restrict__ bst,
                                     float* __restrict__ owt) {
    int idx = blockIdx.x * 256 + threadIdx.x;
    if (idx < K2 * OO * CC) {
        int k = idx / (OO * CC);
        int r = idx % (OO * CC);
        int o = r / CC;
        int c = r % CC;
        float v = cw[(size_t)(o * CC + c) * K2 + k];
        __nv_bfloat16 h = __float2bfloat16(v);
        __nv_bfloat16 l = __float2bfloat16(v - __bfloat162float(h));
        uint32_t sw = SW128((uint32_t)(o * 128 + c * 2)) >> 1;
        bst[(k * 2 + 0) * 4096 + sw] = *(ushort_t*)&h;
        bst[(k * 2 + 1) * 4096 + sw] = *(ushort_t*)&l;
    }
    if (idx < NOFF * CC * K2) {
        int j = idx / (CC * K2);
        int r = idx % (CC * K2);
        int c = r / K2;
        int k = r % K2;
        owt[(c * K2 + k) * 20 + j] = ow[idx];
    }
}

// ---------------- offset conv + position precompute -----------------------------
__global__ void __launch_bounds__(256) offset_conv_kernel(
    const float* __restrict__ x, const float* __restrict__ owt,
    const float* __restrict__ ob, int* __restrict__ pidx, float2* __restrict__ pw2)
{
    __shared__ float ws[CC * K2 * 20];
    __shared__ float bs[NOFF];
    int tid = threadIdx.x;
    for (int i = tid; i < CC * K2 * 20; i += 256) ws[i] = owt[i];
    if (tid < NOFF) bs[tid] = ob[tid];
    __syncthreads();

    int flat = blockIdx.x * 256 + tid;
    int b = flat / HW, p = flat % HW;
    int h = p / WW, w = p % WW;
    const float* x0 = x + (size_t)b * CC * HW;

    ull a0[9];
#pragma unroll
    for (int j = 0; j < 9; j++) a0[j] = 0ull;

    int yy[3], xx[3]; bool vy[3], vx[3];
#pragma unroll
    for (int d = 0; d < 3; d++) {
        yy[d] = h + d - 1; vy[d] = (unsigned)yy[d] < (unsigned)HH;
        xx[d] = w + d - 1; vx[d] = (unsigned)xx[d] < (unsigned)WW;
    }
    for (int c = 0; c < CC; c++) {
        float xv[9];
        const float* xc = x0 + (size_t)c * HW;
#pragma unroll
        for (int dy = 0; dy < 3; dy++)
#pragma unroll
            for (int dx = 0; dx < 3; dx++) {
                int i = dy * 3 + dx;
                xv[i] = (vy[dy] && vx[dx]) ? xc[yy[dy] * WW + xx[dx]] : 0.f;
            }
#pragma unroll
        for (int i = 0; i < 9; i++) {
            const float* row = ws + (c * K2 + i) * 20;
            ull s0;
            PACKF2(s0, xv[i], xv[i]);
#pragma unroll
            for (int j = 0; j < 9; j++) {
                ull wv = *(const ull*)(row + 2 * j);
                FMA2(a0[j], s0, wv, a0[j]);
            }
        }
    }
#pragma unroll
    for (int t = 0; t < 9; t++) {
        float dy, dx;
        UNPKF2(dy, dx, a0[t]);
        dy += bs[2 * t];
        dx += bs[2 * t + 1];
        float py = (float)(h - 1 + t / 3) + dy;
        float qx = (float)(w - 1 + t % 3) + dx;
        float fy = floorf(py), fx = floorf(qx);
        int y0 = (int)fy, x0i = (int)fx;
        float wy = py - fy, wx = qx - fx;
        bool far = (y0 < -2) | (y0 > 96) | (x0i < -2) | (x0i > 96);
        int idx = far ? 0 : ((y0 + 2) * WP + (x0i + 2)) * CC;
        size_t gp = ((size_t)(b * 9 + t)) * HW + p;
        pidx[gp] = idx;
        pw2[gp]  = make_float2(wy, wx);
    }
}

// ---------------- fused: 64-px tile, 3 CTAs/SM, SW128, cp.async, HMMA -----------
// smem (bytes): A 2buf x (hi 8192 + lo 8192) = 32768
//               B at 32768: 2buf x (hi 8192 + lo 8192) = 32768
//               sIdx at 65536 (576 int), sFrac at 67840 (576 float2)
#define SM_B    32768
#define SM_IDX  65536
#define SM_FR   67840
#define SM_TOT  72448

__global__ void __launch_bounds__(256, 3)
fused_mma_kernel(const float* __restrict__ xt, const int* __restrict__ pidx,
                 const float2* __restrict__ pw2, const ushort_t* __restrict__ bst,
                 const float* __restrict__ cb, float* __restrict__ out)
{
    extern __shared__ char smc[];
    uint32_t sbase = smem_u32(smc);
    int tid = threadIdx.x, wid = tid >> 5, lane = tid & 31;
    int b  = blockIdx.x / 144;
    int p0 = (blockIdx.x % 144) * 64;

    const float* xt_b = xt + (size_t)b * XTB;
    int c2 = 2 * lane;
    int*    sIdx = (int*)(smc + SM_IDX);
    float2* sFr  = (float2*)(smc + SM_FR);

    int mt = wid & 3;       // m16 tile
    int nh = wid >> 2;      // N half (4 n8 tiles)

    float acc[4][4];
#pragma unroll
    for (int i = 0; i < 4; i++)
#pragma unroll
        for (int j = 0; j < 4; j++) acc[i][j] = 0.f;

    int lr = lane & 7;
    uint32_t la0 = (uint32_t)((mt * 16 + lr + ((lane >> 3) & 1) * 8) * 128 + (lane >> 4) * 16);
    uint32_t lb0 = (uint32_t)((lr + (lane >> 4) * 8) * 128 + ((lane >> 3) & 1) * 16);

    auto stageB = [&](int k, int buf) {
        const char* src = (const char*)(bst) + (size_t)k * 16384;
        uint32_t dst = sbase + SM_B + (uint32_t)buf * 16384;
#pragma unroll
        for (int i = 0; i < 4; i++) {
            int e = tid + 256 * i;
            CP_ASYNC16(dst + (uint32_t)e * 16, src + (size_t)e * 16);
        }
        CP_COMMIT();
    };
    auto fill = [&](int k, int buf) {
        const int*    si = sIdx + (k << 6);
        const float2* sf = sFr  + (k << 6);
        char* Ab = smc + buf * 16384;
#pragma unroll
        for (int j = 0; j < 8; j++) {
            int px = wid + 8 * j;
            int idx = si[px];
            float2 fr = sf[px];
            const float* base = xt_b + idx + c2;
            float2 g00 = *(const float2*)(base);
            float2 g01 = *(const float2*)(base + CC);
            float2 g10 = *(const float2*)(base + WP * CC);
            float2 g11 = *(const float2*)(base + WP * CC + CC);
            float wy = fr.x, wx = fr.y;
            float w00 = (1.f - wy) * (1.f - wx);
            float w01 = (1.f - wy) * wx;
            float w10 = wy * (1.f - wx);
            float w11 = wy * wx;
            float sx = g00.x*w00 + g01.x*w01 + g10.x*w10 + g11.x*w11;
            float sy = g00.y*w00 + g01.y*w01 + g10.y*w10 + g11.y*w11;
            uint32_t hp, lp;
            asm("cvt.rn.bf16x2.f32 %0, %1, %2;" : "=r"(hp) : "f"(sy), "f"(sx));
            float hx = __uint_as_float(hp << 16);
            float hy = __uint_as_float(hp & 0xffff0000u);
            asm("cvt.rn.bf16x2.f32 %0, %1, %2;" : "=r"(lp) : "f"(sy - hy), "f"(sx - hx));
            uint32_t sw = SW128((uint32_t)(px * 128 + lane * 4));
            *(uint32_t*)(Ab + sw)        = hp;
            *(uint32_t*)(Ab + 8192 + sw) = lp;
        }
    };

    // ---- prologue: idx/frac for all 9 taps, stage B0, fill A0 ----
    {
        size_t gb = (size_t)(b * 9) * HW + p0;
        for (int i = tid; i < 576; i += 256) {
            int t = i >> 6, px = i & 63;
            size_t g = gb + (size_t)t * HW + px;
            sIdx[i] = pidx[g];
            sFr[i]  = pw2[g];
        }
    }
    stageB(0, 0);
    __syncthreads();
    fill(0, 0);
    CP_WAIT0();
    __syncthreads();

    for (int k = 0; k < 9; k++) {
        int buf = k & 1;
        if (k < 8) stageB(k + 1, buf ^ 1);

        uint32_t Abase = sbase + (uint32_t)buf * 16384;
        uint32_t Bbase = sbase + SM_B + (uint32_t)buf * 16384;
#pragma unroll
        for (int ks = 0; ks < 4; ks++) {
            uint32_t la = SW128(la0 + ks * 32);
            uint32_t ah0, ah1, ah2, ah3, al0, al1, al2, al3;
            LDSM_X4(ah0, ah1, ah2, ah3, Abase + la);
            LDSM_X4(al0, al1, al2, al3, Abase + la + 8192);
            uint32_t bh[2][4];
#pragma unroll
            for (int q = 0; q < 2; q++) {
                uint32_t lb = SW128(lb0 + (uint32_t)((2 * nh + q) * 2048) + ks * 32);
                LDSM_X4(bh[q][0], bh[q][1], bh[q][2], bh[q][3], Bbase + lb);
            }
#pragma unroll
            for (int nt = 0; nt < 4; nt++) {
                uint32_t* bq = bh[nt >> 1];
                int e = (nt & 1) * 2;
                MMA16816(acc[nt], ah0, ah1, ah2, ah3, bq[e], bq[e + 1]);
            }
#pragma unroll
            for (int nt = 0; nt < 4; nt++) {
                uint32_t* bq = bh[nt >> 1];
                int e = (nt & 1) * 2;
                MMA16816(acc[nt], al0, al1, al2, al3, bq[e], bq[e + 1]);
            }
            uint32_t bl[2][4];
#pragma unroll
            for (int q = 0; q < 2; q++) {
                uint32_t lb = SW128(lb0 + (uint32_t)((2 * nh + q) * 2048) + ks * 32);
                LDSM_X4(bl[q][0], bl[q][1], bl[q][2], bl[q][3], Bbase + 8192 + lb);
            }
#pragma unroll
            for (int nt = 0; nt < 4; nt++) {
                uint32_t* bq = bl[nt >> 1];
                int e = (nt & 1) * 2;
                MMA16816(acc[nt], ah0, ah1, ah2, ah3, bq[e], bq[e + 1]);
            }
        }

        if (k < 8) {
            fill(k + 1, buf ^ 1);
            CP_WAIT0();
        }
        __syncthreads();
    }

    // ---- epilogue ----
    int px0 = p0 + mt * 16 + (lane >> 2);
    int ob0 = 2 * (lane & 3);
    float* outb = out + (size_t)b * OO * HW;
#pragma unroll
    for (int nt = 0; nt < 4; nt++) {
        int o = (4 * nh + nt) * 8 + ob0;
        float b0 = cb[o], b1 = cb[o + 1];
        outb[(size_t)o * HW + px0]           = acc[nt][0] + b0;
        outb[(size_t)(o + 1) * HW + px0]     = acc[nt][1] + b1;
        outb[(size_t)o * HW + px0 + 8]       = acc[nt][2] + b0;
        outb[(size_t)(o + 1) * HW + px0 + 8] = acc[nt][3] + b1;
    }
}

// ---------------- launch ---------------------------------------------------------
extern "C" void kernel_launch(void* const* d_in, const int* in_sizes, int n_in,
                              void* d_out, int out_size) {
    const float* x  = (const float*)d_in[0];
    const float* ow = (const float*)d_in[1];
    const float* ob = (const float*)d_in[2];
    const float* cw = (const float*)d_in[3];
    const float* cb = (const float*)d_in[4];
    float* out = (float*)d_out;

    float *xt, *owt;
    int* pidx;
    float2* pw2;
    ushort_t* bst;
    cudaGetSymbolAddress((void**)&xt,   g_xt);
    cudaGetSymbolAddress((void**)&owt,  g_owt);
    cudaGetSymbolAddress((void**)&pidx, g_pidx);
    cudaGetSymbolAddress((void**)&pw2,  g_pw2);
    cudaGetSymbolAddress((void**)&bst,  g_bst);

    cudaFuncSetAttribute(fused_mma_kernel,
                         cudaFuncAttributeMaxDynamicSharedMemorySize, SM_TOT);

    transpose_x_kernel<<<4608, 256>>>(x, xt);
    build_weights_kernel<<<144, 256>>>(cw, ow, bst, owt);
    offset_conv_kernel<<<288, 256>>>(x, owt, ob, pidx, pw2);
    fused_mma_kernel<<<1152, 256, SM_TOT>>>(xt, pidx, pw2, bst, cb, out);
}

// round 13
// speedup vs baseline: 1.1682x; 1.0004x over previous
#include <cuda_runtime.h>
#include <cuda_bf16.h>
#include <cstdint>

#define BB 8
#define CC 64
#define OO 64
#define HH 96
#define WW 96
#define HW (HH*WW)
#define K2 9
#define NOFF 18
#define WP 100              // padded width/height
#define XTB (WP*WP*CC)

typedef unsigned long long ull;
typedef unsigned short ushort_t;

#define PACKF2(d, lo, hi) asm("mov.b64 %0, {%1,%2};" : "=l"(d) : "f"(lo), "f"(hi))
#define UNPKF2(lo, hi, s) asm("mov.b64 {%0,%1}, %2;" : "=f"(lo), "=f"(hi) : "l"(s))
#define FMA2(d, a, b, c)  asm("fma.rn.f32x2 %0, %1, %2, %3;" : "=l"(d) : "l"(a), "l"(b), "l"(c))
#define SW128(off) ((off) ^ (((off) >> 3) & 0x70))

__device__ __forceinline__ uint32_t smem_u32(const void* p) {
    uint32_t a;
    asm("{ .reg .u64 t; cvta.to.shared.u64 t, %1; cvt.u32.u64 %0, t; }" : "=r"(a) : "l"(p));
    return a;
}

#define LDSM_X4(r0, r1, r2, r3, addr) \
    asm volatile("ldmatrix.sync.aligned.m8n8.x4.shared.b16 {%0,%1,%2,%3}, [%4];" \
                 : "=r"(r0), "=r"(r1), "=r"(r2), "=r"(r3) : "r"(addr))

#define MMA16816(ac, a0, a1, a2, a3, b0, b1) \
    asm volatile("mma.sync.aligned.m16n8k16.row.col.f32.bf16.bf16.f32 " \
                 "{%0,%1,%2,%3}, {%4,%5,%6,%7}, {%8,%9}, {%0,%1,%2,%3};" \
                 : "+f"((ac)[0]), "+f"((ac)[1]), "+f"((ac)[2]), "+f"((ac)[3]) \
                 : "r"(a0), "r"(a1), "r"(a2), "r"(a3), "r"(b0), "r"(b1))

#define CP_ASYNC16(dst, src) \
    asm volatile("cp.async.cg.shared.global [%0], [%1], 16;" :: "r"(dst), "l"(src))
#define CP_COMMIT() asm volatile("cp.async.commit_group;")
#define CP_WAIT0()  asm volatile("cp.async.wait_group 0;")

// ---------------- scratch -----------------------------------------------------
__device__ float   g_xt[BB * XTB];             // padded NHWC x (zero border)
__device__ int     g_pidx[BB * K2 * HW];       // base idx (0 => zero corner if far)
__device__ float2  g_pw2[BB * K2 * HW];        // raw fractions (wy, wx)
__device__ float   g_owt[CC * K2 * 20];
__device__ ushort_t g_bst[K2 * 2 * 4096];      // conv_w bf16 [tap][hi/lo], SW128-swizzled

// ---------------- transpose NCHW -> padded NHWC --------------------------------
__global__ void transpose_x_kernel(const float* __restrict__ x, float* __restrict__ xt) {
    __shared__ float tile[32][33];
    int blk = blockIdx.x;
    int pt = blk % 288, ct = (blk / 288) & 1, b = blk / 576;
    int lx = threadIdx.x & 31, ly = threadIdx.x >> 5;
    int p0 = pt * 32, c0 = ct * 32;
    int h = p0 / WW, w0 = p0 - h * WW;
    const float* xb = x + (size_t)(b * CC + c0) * HW + p0;
#pragma unroll
    for (int i = 0; i < 4; i++) {
        int cc = ly + 8 * i;
        tile[cc][lx] = xb[(size_t)cc * HW + lx];
    }
    __syncthreads();
    float* xo = xt + (size_t)b * XTB + ((size_t)(h + 2) * WP + (w0 + 2)) * CC + c0;
#pragma unroll
    for (int i = 0; i < 4; i++) {
        int pp = ly + 8 * i;
        xo[(size_t)pp * CC + lx] = tile[lx][pp];
    }
}

// ---------------- weight prep (B pre-swizzled) ----------------------------------
__global__ void build_weights_kernel(const float* __restrict__ cw,
                                     const float* __restrict__ ow,
                                     ushort_t* __restrict__ bst,
                                     float* __restrict__ owt) {
    int idx = blockIdx.x * 256 + threadIdx.x;
    if (idx < K2 * OO * CC) {
        int k = idx / (OO * CC);
        int r = idx % (OO * CC);
        int o = r / CC;
        int c = r % CC;
        float v = cw[(size_t)(o * CC + c) * K2 + k];
        __nv_bfloat16 h = __float2bfloat16(v);
        __nv_bfloat16 l = __float2bfloat16(v - __bfloat162float(h));
        uint32_t sw = SW128((uint32_t)(o * 128 + c * 2)) >> 1;
        bst[(k * 2 + 0) * 4096 + sw] = *(ushort_t*)&h;
        bst[(k * 2 + 1) * 4096 + sw] = *(ushort_t*)&l;
    }
    if (idx < NOFF * CC * K2) {
        int j = idx / (CC * K2);
        int r = idx % (CC * K2);
        int c = r / K2;
        int k = r % K2;
        owt[(c * K2 + k) * 20 + j] = ow[idx];
    }
}

// ---------------- offset conv + position precompute -----------------------------
__global__ void __launch_bounds__(256) offset_conv_kernel(
    const float* __restrict__ x, const float* __restrict__ owt,
    const float* __restrict__ ob, int* __restrict__ pidx, float2* __restrict__ pw2)
{
    __shared__ float ws[CC * K2 * 20];
    __shared__ float bs[NOFF];
    int tid = threadIdx.x;
    for (int i = tid; i < CC * K2 * 20; i += 256) ws[i] = owt[i];
    if (tid < NOFF) bs[tid] = ob[tid];
    __syncthreads();

    int flat = blockIdx.x * 256 + tid;
    int b = flat / HW, p = flat % HW;
    int h = p / WW, w = p % WW;
    const float* x0 = x + (size_t)b * CC * HW;

    ull a0[9];
#pragma unroll
    for (int j = 0; j < 9; j++) a0[j] = 0ull;

    int yy[3], xx[3]; bool vy[3], vx[3];
#pragma unroll
    for (int d = 0; d < 3; d++) {
        yy[d] = h + d - 1; vy[d] = (unsigned)yy[d] < (unsigned)HH;
        xx[d] = w + d - 1; vx[d] = (unsigned)xx[d] < (unsigned)WW;
    }
    for (int c = 0; c < CC; c++) {
        float xv[9];
        const float* xc = x0 + (size_t)c * HW;
#pragma unroll
        for (int dy = 0; dy < 3; dy++)
#pragma unroll
            for (int dx = 0; dx < 3; dx++) {
                int i = dy * 3 + dx;
                xv[i] = (vy[dy] && vx[dx]) ? xc[yy[dy] * WW + xx[dx]] : 0.f;
            }
#pragma unroll
        for (int i = 0; i < 9; i++) {
            const float* row = ws + (c * K2 + i) * 20;
            ull s0;
            PACKF2(s0, xv[i], xv[i]);
#pragma unroll
            for (int j = 0; j < 9; j++) {
                ull wv = *(const ull*)(row + 2 * j);
                FMA2(a0[j], s0, wv, a0[j]);
            }
        }
    }
#pragma unroll
    for (int t = 0; t < 9; t++) {
        float dy, dx;
        UNPKF2(dy, dx, a0[t]);
        dy += bs[2 * t];
        dx += bs[2 * t + 1];
        float py = (float)(h - 1 + t / 3) + dy;
        float qx = (float)(w - 1 + t % 3) + dx;
        float fy = floorf(py), fx = floorf(qx);
        int y0 = (int)fy, x0i = (int)fx;
        float wy = py - fy, wx = qx - fx;
        bool far = (y0 < -2) | (y0 > 96) | (x0i < -2) | (x0i > 96);
        int idx = far ? 0 : ((y0 + 2) * WP + (x0i + 2)) * CC;
        size_t gp = ((size_t)(b * 9 + t)) * HW + p;
        pidx[gp] = idx;
        pw2[gp]  = make_float2(wy, wx);
    }
}

// ---------------- fused: 64-px tile, 512 thr, 2 CTAs/SM (32 warps), HMMA --------
// warp roles: mt = wid & 3 (m16 tile), nq = wid >> 2 (2 n8-tiles each)
// smem (bytes): A 2buf x (hi 8192 + lo 8192) = 32768
//               B at 32768: 2buf x 16384 = 32768
//               sIdx at 65536 (576 int), sFrac at 67840 (576 float2)
#define SM_B    32768
#define SM_IDX  65536
#define SM_FR   67840
#define SM_TOT  72448

__global__ void __launch_bounds__(512, 2)
fused_mma_kernel(const float* __restrict__ xt, const int* __restrict__ pidx,
                 const float2* __restrict__ pw2, const ushort_t* __restrict__ bst,
                 const float* __restrict__ cb, float* __restrict__ out)
{
    extern __shared__ char smc[];
    uint32_t sbase = smem_u32(smc);
    int tid = threadIdx.x, wid = tid >> 5, lane = tid & 31;
    int b  = blockIdx.x / 144;
    int p0 = (blockIdx.x % 144) * 64;

    const float* xt_b = xt + (size_t)b * XTB;
    int c2 = 2 * lane;
    int*    sIdx = (int*)(smc + SM_IDX);
    float2* sFr  = (float2*)(smc + SM_FR);

    int mt = wid & 3;       // m16 tile
    int nq = wid >> 2;      // n quarter: 2 n8-tiles

    float acc[2][4];
#pragma unroll
    for (int i = 0; i < 2; i++)
#pragma unroll
        for (int j = 0; j < 4; j++) acc[i][j] = 0.f;

    int lr = lane & 7;
    uint32_t la0 = (uint32_t)((mt * 16 + lr + ((lane >> 3) & 1) * 8) * 128 + (lane >> 4) * 16);
    uint32_t lb0 = (uint32_t)((lr + (lane >> 4) * 8) * 128 + ((lane >> 3) & 1) * 16)
                 + (uint32_t)(nq * 2048);

    auto stageB = [&](int k, int buf) {
        const char* src = (const char*)(bst) + (size_t)k * 16384;
        uint32_t dst = sbase + SM_B + (uint32_t)buf * 16384;
#pragma unroll
        for (int i = 0; i < 2; i++) {
            int e = tid + 512 * i;
            CP_ASYNC16(dst + (uint32_t)e * 16, src + (size_t)e * 16);
        }
        CP_COMMIT();
    };
    auto fill = [&](int k, int buf) {
        const int*    si = sIdx + (k << 6);
        const float2* sf = sFr  + (k << 6);
        char* Ab = smc + buf * 16384;
#pragma unroll
        for (int j = 0; j < 4; j++) {
            int px = wid + 16 * j;
            int idx = si[px];
            float2 fr = sf[px];
            const float* base = xt_b + idx + c2;
            float2 g00 = *(const float2*)(base);
            float2 g01 = *(const float2*)(base + CC);
            float2 g10 = *(const float2*)(base + WP * CC);
            float2 g11 = *(const float2*)(base + WP * CC + CC);
            float wy = fr.x, wx = fr.y;
            float w00 = (1.f - wy) * (1.f - wx);
            float w01 = (1.f - wy) * wx;
            float w10 = wy * (1.f - wx);
            float w11 = wy * wx;
            float sx = g00.x*w00 + g01.x*w01 + g10.x*w10 + g11.x*w11;
            float sy = g00.y*w00 + g01.y*w01 + g10.y*w10 + g11.y*w11;
            uint32_t hp, lp;
            asm("cvt.rn.bf16x2.f32 %0, %1, %2;" : "=r"(hp) : "f"(sy), "f"(sx));
            float hx = __uint_as_float(hp << 16);
            float hy = __uint_as_float(hp & 0xffff0000u);
            asm("cvt.rn.bf16x2.f32 %0, %1, %2;" : "=r"(lp) : "f"(sy - hy), "f"(sx - hx));
            uint32_t sw = SW128((uint32_t)(px * 128 + lane * 4));
            *(uint32_t*)(Ab + sw)        = hp;
            *(uint32_t*)(Ab + 8192 + sw) = lp;
        }
    };

    // ---- prologue: idx/frac for all 9 taps, stage B0, fill A0 ----
    {
        size_t gb = (size_t)(b * 9) * HW + p0;
        for (int i = tid; i < 576; i += 512) {
            int t = i >> 6, px = i & 63;
            size_t g = gb + (size_t)t * HW + px;
            sIdx[i] = pidx[g];
            sFr[i]  = pw2[g];
        }
    }
    stageB(0, 0);
    __syncthreads();
    fill(0, 0);
    CP_WAIT0();
    __syncthreads();

    for (int k = 0; k < 9; k++) {
        int buf = k & 1;
        if (k < 8) stageB(k + 1, buf ^ 1);

        uint32_t Abase = sbase + (uint32_t)buf * 16384;
        uint32_t Bbase = sbase + SM_B + (uint32_t)buf * 16384;
#pragma unroll
        for (int ks = 0; ks < 4; ks++) {
            uint32_t la = SW128(la0 + ks * 32);
            uint32_t lb = SW128(lb0 + ks * 32);
            uint32_t ah0, ah1, ah2, ah3, al0, al1, al2, al3;
            LDSM_X4(ah0, ah1, ah2, ah3, Abase + la);
            LDSM_X4(al0, al1, al2, al3, Abase + la + 8192);
            uint32_t bh[4];
            LDSM_X4(bh[0], bh[1], bh[2], bh[3], Bbase + lb);
            MMA16816(acc[0], ah0, ah1, ah2, ah3, bh[0], bh[1]);
            MMA16816(acc[1], ah0, ah1, ah2, ah3, bh[2], bh[3]);
            MMA16816(acc[0], al0, al1, al2, al3, bh[0], bh[1]);
            MMA16816(acc[1], al0, al1, al2, al3, bh[2], bh[3]);
            uint32_t bl[4];
            LDSM_X4(bl[0], bl[1], bl[2], bl[3], Bbase + 8192 + lb);
            MMA16816(acc[0], ah0, ah1, ah2, ah3, bl[0], bl[1]);
            MMA16816(acc[1], ah0, ah1, ah2, ah3, bl[2], bl[3]);
        }

        if (k < 8) {
            fill(k + 1, buf ^ 1);
            CP_WAIT0();
        }
        __syncthreads();
    }

    // ---- epilogue ----
    int px0 = p0 + mt * 16 + (lane >> 2);
    int ob0 = 2 * (lane & 3);
    float* outb = out + (size_t)b * OO * HW;
#pragma unroll
    for (int nt = 0; nt < 2; nt++) {
        int o = (nq * 2 + nt) * 8 + ob0;
        float b0 = cb[o], b1 = cb[o + 1];
        outb[(size_t)o * HW + px0]           = acc[nt][0] + b0;
        outb[(size_t)(o + 1) * HW + px0]     = acc[nt][1] + b1;
        outb[(size_t)o * HW + px0 + 8]       = acc[nt][2] + b0;
        outb[(size_t)(o + 1) * HW + px0 + 8] = acc[nt][3] + b1;
    }
}

// ---------------- launch ---------------------------------------------------------
extern "C" void kernel_launch(void* const* d_in, const int* in_sizes, int n_in,
                              void* d_out, int out_size) {
    const float* x  = (const float*)d_in[0];
    const float* ow = (const float*)d_in[1];
    const float* ob = (const float*)d_in[2];
    const float* cw = (const float*)d_in[3];
    const float* cb = (const float*)d_in[4];
    float* out = (float*)d_out;

    float *xt, *owt;
    int* pidx;
    float2* pw2;
    ushort_t* bst;
    cudaGetSymbolAddress((void**)&xt,   g_xt);
    cudaGetSymbolAddress((void**)&owt,  g_owt);
    cudaGetSymbolAddress((void**)&pidx, g_pidx);
    cudaGetSymbolAddress((void**)&pw2,  g_pw2);
    cudaGetSymbolAddress((void**)&bst,  g_bst);

    cudaFuncSetAttribute(fused_mma_kernel,
                         cudaFuncAttributeMaxDynamicSharedMemorySize, SM_TOT);

    transpose_x_kernel<<<4608, 256>>>(x, xt);
    build_weights_kernel<<<144, 256>>>(cw, ow, bst, owt);
    offset_conv_kernel<<<288, 256>>>(x, owt, ob, pidx, pw2);
    fused_mma_kernel<<<1152, 512, SM_TOT>>>(xt, pidx, pw2, bst, cb, out);
}

// round 14
// speedup vs baseline: 1.3236x; 1.1330x over previous
#include <cuda_runtime.h>
#include <cuda_bf16.h>
#include <cstdint>

#define BB 8
#define CC 64
#define OO 64
#define HH 96
#define WW 96
#define HW (HH*WW)
#define K2 9
#define NOFF 18
#define WP 100              // padded width/height
#define XTB (WP*WP*CC)

typedef unsigned long long ull;
typedef unsigned short ushort_t;

#define SW128(off) ((off) ^ (((off) >> 3) & 0x70))

__device__ __forceinline__ uint32_t smem_u32(const void* p) {
    uint32_t a;
    asm("{ .reg .u64 t; cvta.to.shared.u64 t, %1; cvt.u32.u64 %0, t; }" : "=r"(a) : "l"(p));
    return a;
}

#define LDSM_X4(r0, r1, r2, r3, addr) \
    asm volatile("ldmatrix.sync.aligned.m8n8.x4.shared.b16 {%0,%1,%2,%3}, [%4];" \
                 : "=r"(r0), "=r"(r1), "=r"(r2), "=r"(r3) : "r"(addr))

#define MMA16816(ac, a0, a1, a2, a3, b0, b1) \
    asm volatile("mma.sync.aligned.m16n8k16.row.col.f32.bf16.bf16.f32 " \
                 "{%0,%1,%2,%3}, {%4,%5,%6,%7}, {%8,%9}, {%0,%1,%2,%3};" \
                 : "+f"((ac)[0]), "+f"((ac)[1]), "+f"((ac)[2]), "+f"((ac)[3]) \
                 : "r"(a0), "r"(a1), "r"(a2), "r"(a3), "r"(b0), "r"(b1))

#define CP_ASYNC16(dst, src) \
    asm volatile("cp.async.cg.shared.global [%0], [%1], 16;" :: "r"(dst), "l"(src))
#define CP_COMMIT() asm volatile("cp.async.commit_group;")
#define CP_WAIT0()  asm volatile("cp.async.wait_group 0;")

#define BF16_SPLIT(sx, sy, hp, lp) do { \
    asm("cvt.rn.bf16x2.f32 %0, %1, %2;" : "=r"(hp) : "f"(sy), "f"(sx)); \
    float _hx = __uint_as_float((hp) << 16); \
    float _hy = __uint_as_float((hp) & 0xffff0000u); \
    asm("cvt.rn.bf16x2.f32 %0, %1, %2;" : "=r"(lp) : "f"((sy) - _hy), "f"((sx) - _hx)); \
} while (0)

// ---------------- scratch -----------------------------------------------------
__device__ float   g_xt[BB * XTB];             // padded NHWC x (zero border)
__device__ int     g_pidx[BB * K2 * HW];       // base idx (0 => zero corner if far)
__device__ float2  g_pw2[BB * K2 * HW];        // raw fractions (wy, wx)
__device__ ushort_t g_bst[K2 * 2 * 4096];      // conv_w bf16 [tap][hi/lo], SW128
__device__ ushort_t g_obst[K2 * 2 * 2048];     // offset_w bf16 [tap][hi/lo][32n][64c], SW128

// ---------------- transpose NCHW -> padded NHWC --------------------------------
__global__ void transpose_x_kernel(const float* __restrict__ x, float* __restrict__ xt) {
    __shared__ float tile[32][33];
    int blk = blockIdx.x;
    int pt = blk % 288, ct = (blk / 288) & 1, b = blk / 576;
    int lx = threadIdx.x & 31, ly = threadIdx.x >> 5;
    int p0 = pt * 32, c0 = ct * 32;
    int h = p0 / WW, w0 = p0 - h * WW;
    const float* xb = x + (size_t)(b * CC + c0) * HW + p0;
#pragma unroll
    for (int i = 0; i < 4; i++) {
        int cc = ly + 8 * i;
        tile[cc][lx] = xb[(size_t)cc * HW + lx];
    }
    __syncthreads();
    float* xo = xt + (size_t)b * XTB + ((size_t)(h + 2) * WP + (w0 + 2)) * CC + c0;
#pragma unroll
    for (int i = 0; i < 4; i++) {
        int pp = ly + 8 * i;
        xo[(size_t)pp * CC + lx] = tile[lx][pp];
    }
}

// ---------------- weight prep (both B matrices pre-swizzled) --------------------
__global__ void build_weights_kernel(const float* __restrict__ cw,
                                     const float* __restrict__ ow,
                                     ushort_t* __restrict__ bst,
                                     ushort_t* __restrict__ obst) {
    int idx = blockIdx.x * 256 + threadIdx.x;
    if (idx < K2 * OO * CC) {        // conv_w -> [tap][hi/lo][64o][64c]
        int k = idx / (OO * CC);
        int r = idx % (OO * CC);
        int o = r / CC;
        int c = r % CC;
        float v = cw[(size_t)(o * CC + c) * K2 + k];
        __nv_bfloat16 h = __float2bfloat16(v);
        __nv_bfloat16 l = __float2bfloat16(v - __bfloat162float(h));
        uint32_t sw = SW128((uint32_t)(o * 128 + c * 2)) >> 1;
        bst[(k * 2 + 0) * 4096 + sw] = *(ushort_t*)&h;
        bst[(k * 2 + 1) * 4096 + sw] = *(ushort_t*)&l;
    }
    if (idx < K2 * 32 * CC) {        // offset_w -> [tap][hi/lo][32n pad][64c]
        int k = idx / (32 * CC);
        int r = idx % (32 * CC);
        int n = r / CC;
        int c = r % CC;
        float v = (n < NOFF) ? ow[(size_t)(n * CC + c) * K2 + k] : 0.f;
        __nv_bfloat16 h = __float2bfloat16(v);
        __nv_bfloat16 l = __float2bfloat16(v - __bfloat162float(h));
        uint32_t sw = SW128((uint32_t)(n * 128 + c * 2)) >> 1;
        obst[(k * 2 + 0) * 2048 + sw] = *(ushort_t*)&h;
        obst[(k * 2 + 1) * 2048 + sw] = *(ushort_t*)&l;
    }
}

// ---------------- offset conv as HMMA + fused position precompute ---------------
// 256 thr, tile 64 px x 32 out (N=18 padded), 4 CTAs/SM.
// smem: A 2buf x (hi 8192 + lo 8192) = 32768; B at 32768: 2buf x (hi 4096 + lo 4096)
#define OSM_B   32768
#define OSM_TOT 49152

__global__ void __launch_bounds__(256, 4)
offset_mma_kernel(const float* __restrict__ xt, const ushort_t* __restrict__ obst,
                  const float* __restrict__ ob,
                  int* __restrict__ pidx, float2* __restrict__ pw2)
{
    extern __shared__ char smc[];
    uint32_t sbase = smem_u32(smc);
    int tid = threadIdx.x, wid = tid >> 5, lane = tid & 31;
    int b  = blockIdx.x / 144;
    int p0 = (blockIdx.x % 144) * 64;

    const float* xt_b = xt + (size_t)b * XTB;
    int c2 = 2 * lane;
    int mt = wid & 3;      // m16 tile
    int ng = wid >> 2;     // n group: 2 n8-tiles (n = ng*16 .. +15)

    float acc[2][4];
#pragma unroll
    for (int i = 0; i < 2; i++)
#pragma unroll
        for (int j = 0; j < 4; j++) acc[i][j] = 0.f;

    int lr = lane & 7;
    uint32_t la0 = (uint32_t)((mt * 16 + lr + ((lane >> 3) & 1) * 8) * 128 + (lane >> 4) * 16);
    uint32_t lb0 = (uint32_t)((ng * 16 + lr + (lane >> 4) * 8) * 128 + ((lane >> 3) & 1) * 16);

    auto stageB = [&](int k, int buf) {
        const char* src = (const char*)(obst) + (size_t)k * 8192;
        uint32_t dst = sbase + OSM_B + (uint32_t)buf * 8192;
        {
            int e = tid;           // 512 uint4 total
            CP_ASYNC16(dst + (uint32_t)e * 16, src + (size_t)e * 16);
            e = tid + 256;
            CP_ASYNC16(dst + (uint32_t)e * 16, src + (size_t)e * 16);
        }
        CP_COMMIT();
    };
    auto fill = [&](int k, int buf) {
        int dyk = k / 3, dxk = k % 3;
        char* Ab = smc + buf * 16384;
#pragma unroll
        for (int j = 0; j < 8; j++) {
            int px = wid + 8 * j;
            int p = p0 + px;
            int h = p / WW, w = p - h * WW;
            const float* base = xt_b + ((size_t)(h + dyk + 1) * WP + (w + dxk + 1)) * CC + c2;
            float2 g = *(const float2*)base;
            uint32_t hp, lp;
            BF16_SPLIT(g.x, g.y, hp, lp);
            uint32_t sw = SW128((uint32_t)(px * 128 + lane * 4));
            *(uint32_t*)(Ab + sw)        = hp;
            *(uint32_t*)(Ab + 8192 + sw) = lp;
        }
    };

    stageB(0, 0);
    fill(0, 0);
    CP_WAIT0();
    __syncthreads();

    for (int k = 0; k < 9; k++) {
        int buf = k & 1;
        if (k < 8) stageB(k + 1, buf ^ 1);

        uint32_t Abase = sbase + (uint32_t)buf * 16384;
        uint32_t Bbase = sbase + OSM_B + (uint32_t)buf * 8192;
#pragma unroll
        for (int ks = 0; ks < 4; ks++) {
            uint32_t la = SW128(la0 + ks * 32);
            uint32_t lb = SW128(lb0 + ks * 32);
            uint32_t ah0, ah1, ah2, ah3, al0, al1, al2, al3;
            LDSM_X4(ah0, ah1, ah2, ah3, Abase + la);
            LDSM_X4(al0, al1, al2, al3, Abase + la + 8192);
            uint32_t bh[4];
            LDSM_X4(bh[0], bh[1], bh[2], bh[3], Bbase + lb);
            MMA16816(acc[0], ah0, ah1, ah2, ah3, bh[0], bh[1]);
            MMA16816(acc[1], ah0, ah1, ah2, ah3, bh[2], bh[3]);
            MMA16816(acc[0], al0, al1, al2, al3, bh[0], bh[1]);
            MMA16816(acc[1], al0, al1, al2, al3, bh[2], bh[3]);
            uint32_t bl[4];
            LDSM_X4(bl[0], bl[1], bl[2], bl[3], Bbase + 4096 + lb);
            MMA16816(acc[0], ah0, ah1, ah2, ah3, bl[0], bl[1]);
            MMA16816(acc[1], ah0, ah1, ah2, ah3, bl[2], bl[3]);
        }

        if (k < 8) {
            fill(k + 1, buf ^ 1);
            CP_WAIT0();
        }
        __syncthreads();
    }

    // ---- epilogue: offsets -> positions, written straight to pidx/pw2 ----
    int px0 = p0 + mt * 16 + (lane >> 2);
#pragma unroll
    for (int nt = 0; nt < 2; nt++) {
        int n0 = ng * 16 + nt * 8 + 2 * (lane & 3);
        int t = n0 >> 1;
        if (t < 9) {
            float bdy = ob[n0], bdx = ob[n0 + 1];
            int tdy = t / 3 - 1, tdx = t % 3 - 1;
#pragma unroll
            for (int half = 0; half < 2; half++) {
                int p = px0 + 8 * half;
                float dy = acc[nt][2 * half]     + bdy;
                float dx = acc[nt][2 * half + 1] + bdx;
                int h = p / WW, w = p - h * WW;
                float py = (float)(h + tdy) + dy;
                float qx = (float)(w + tdx) + dx;
                float fy = floorf(py), fx = floorf(qx);
                int y0 = (int)fy, x0i = (int)fx;
                float wy = py - fy, wx = qx - fx;
                bool far = (y0 < -2) | (y0 > 96) | (x0i < -2) | (x0i > 96);
                int idx = far ? 0 : ((y0 + 2) * WP + (x0i + 2)) * CC;
                size_t gp = ((size_t)(b * 9 + t)) * HW + p;
                pidx[gp] = idx;
                pw2[gp]  = make_float2(wy, wx);
            }
        }
    }
}

// ---------------- fused: 64-px tile, 512 thr, 2 CTAs/SM (32 warps), HMMA --------
#define SM_B    32768
#define SM_IDX  65536
#define SM_FR   67840
#define SM_TOT  72448

__global__ void __launch_bounds__(512, 2)
fused_mma_kernel(const float* __restrict__ xt, const int* __restrict__ pidx,
                 const float2* __restrict__ pw2, const ushort_t* __restrict__ bst,
                 const float* __restrict__ cb, float* __restrict__ out)
{
    extern __shared__ char smc[];
    uint32_t sbase = smem_u32(smc);
    int tid = threadIdx.x, wid = tid >> 5, lane = tid & 31;
    int b  = blockIdx.x / 144;
    int p0 = (blockIdx.x % 144) * 64;

    const float* xt_b = xt + (size_t)b * XTB;
    int c2 = 2 * lane;
    int*    sIdx = (int*)(smc + SM_IDX);
    float2* sFr  = (float2*)(smc + SM_FR);

    int mt = wid & 3;
    int nq = wid >> 2;

    float acc[2][4];
#pragma unroll
    for (int i = 0; i < 2; i++)
#pragma unroll
        for (int j = 0; j < 4; j++) acc[i][j] = 0.f;

    int lr = lane & 7;
    uint32_t la0 = (uint32_t)((mt * 16 + lr + ((lane >> 3) & 1) * 8) * 128 + (lane >> 4) * 16);
    uint32_t lb0 = (uint32_t)((lr + (lane >> 4) * 8) * 128 + ((lane >> 3) & 1) * 16)
                 + (uint32_t)(nq * 2048);

    auto stageB = [&](int k, int buf) {
        const char* src = (const char*)(bst) + (size_t)k * 16384;
        uint32_t dst = sbase + SM_B + (uint32_t)buf * 16384;
#pragma unroll
        for (int i = 0; i < 2; i++) {
            int e = tid + 512 * i;
            CP_ASYNC16(dst + (uint32_t)e * 16, src + (size_t)e * 16);
        }
        CP_COMMIT();
    };
    auto fill = [&](int k, int buf) {
        const int*    si = sIdx + (k << 6);
        const float2* sf = sFr  + (k << 6);
        char* Ab = smc + buf * 16384;
#pragma unroll
        for (int j = 0; j < 4; j++) {
            int px = wid + 16 * j;
            int idx = si[px];
            float2 fr = sf[px];
            const float* base = xt_b + idx + c2;
            float2 g00 = *(const float2*)(base);
            float2 g01 = *(const float2*)(base + CC);
            float2 g10 = *(const float2*)(base + WP * CC);
            float2 g11 = *(const float2*)(base + WP * CC + CC);
            float wy = fr.x, wx = fr.y;
            float w00 = (1.f - wy) * (1.f - wx);
            float w01 = (1.f - wy) * wx;
            float w10 = wy * (1.f - wx);
            float w11 = wy * wx;
            float sx = g00.x*w00 + g01.x*w01 + g10.x*w10 + g11.x*w11;
            float sy = g00.y*w00 + g01.y*w01 + g10.y*w10 + g11.y*w11;
            uint32_t hp, lp;
            BF16_SPLIT(sx, sy, hp, lp);
            uint32_t sw = SW128((uint32_t)(px * 128 + lane * 4));
            *(uint32_t*)(Ab + sw)        = hp;
            *(uint32_t*)(Ab + 8192 + sw) = lp;
        }
    };

    {
        size_t gb = (size_t)(b * 9) * HW + p0;
        for (int i = tid; i < 576; i += 512) {
            int t = i >> 6, px = i & 63;
            size_t g = gb + (size_t)t * HW + px;
            sIdx[i] = pidx[g];
            sFr[i]  = pw2[g];
        }
    }
    stageB(0, 0);
    __syncthreads();
    fill(0, 0);
    CP_WAIT0();
    __syncthreads();

    for (int k = 0; k < 9; k++) {
        int buf = k & 1;
        if (k < 8) stageB(k + 1, buf ^ 1);

        uint32_t Abase = sbase + (uint32_t)buf * 16384;
        uint32_t Bbase = sbase + SM_B + (uint32_t)buf * 16384;
#pragma unroll
        for (int ks = 0; ks < 4; ks++) {
            uint32_t la = SW128(la0 + ks * 32);
            uint32_t lb = SW128(lb0 + ks * 32);
            uint32_t ah0, ah1, ah2, ah3, al0, al1, al2, al3;
            LDSM_X4(ah0, ah1, ah2, ah3, Abase + la);
            LDSM_X4(al0, al1, al2, al3, Abase + la + 8192);
            uint32_t bh[4];
            LDSM_X4(bh[0], bh[1], bh[2], bh[3], Bbase + lb);
            MMA16816(acc[0], ah0, ah1, ah2, ah3, bh[0], bh[1]);
            MMA16816(acc[1], ah0, ah1, ah2, ah3, bh[2], bh[3]);
            MMA16816(acc[0], al0, al1, al2, al3, bh[0], bh[1]);
            MMA16816(acc[1], al0, al1, al2, al3, bh[2], bh[3]);
            uint32_t bl[4];
            LDSM_X4(bl[0], bl[1], bl[2], bl[3], Bbase + 8192 + lb);
            MMA16816(acc[0], ah0, ah1, ah2, ah3, bl[0], bl[1]);
            MMA16816(acc[1], ah0, ah1, ah2, ah3, bl[2], bl[3]);
        }

        if (k < 8) {
            fill(k + 1, buf ^ 1);
            CP_WAIT0();
        }
        __syncthreads();
    }

    int px0 = p0 + mt * 16 + (lane >> 2);
    int ob0 = 2 * (lane & 3);
    float* outb = out + (size_t)b * OO * HW;
#pragma unroll
    for (int nt = 0; nt < 2; nt++) {
        int o = (nq * 2 + nt) * 8 + ob0;
        float b0 = cb[o], b1 = cb[o + 1];
        outb[(size_t)o * HW + px0]           = acc[nt][0] + b0;
        outb[(size_t)(o + 1) * HW + px0]     = acc[nt][1] + b1;
        outb[(size_t)o * HW + px0 + 8]       = acc[nt][2] + b0;
        outb[(size_t)(o + 1) * HW + px0 + 8] = acc[nt][3] + b1;
    }
}

// ---------------- launch ---------------------------------------------------------
extern "C" void kernel_launch(void* const* d_in, const int* in_sizes, int n_in,
                              void* d_out, int out_size) {
    const float* x  = (const float*)d_in[0];
    const float* ow = (const float*)d_in[1];
    const float* ob = (const float*)d_in[2];
    const float* cw = (const float*)d_in[3];
    const float* cb = (const float*)d_in[4];
    float* out = (float*)d_out;

    float* xt;
    int* pidx;
    float2* pw2;
    ushort_t *bst, *obst;
    cudaGetSymbolAddress((void**)&xt,   g_xt);
    cudaGetSymbolAddress((void**)&pidx, g_pidx);
    cudaGetSymbolAddress((void**)&pw2,  g_pw2);
    cudaGetSymbolAddress((void**)&bst,  g_bst);
    cudaGetSymbolAddress((void**)&obst, g_obst);

    cudaFuncSetAttribute(offset_mma_kernel,
                         cudaFuncAttributeMaxDynamicSharedMemorySize, OSM_TOT);
    cudaFuncSetAttribute(fused_mma_kernel,
                         cudaFuncAttributeMaxDynamicSharedMemorySize, SM_TOT);

    transpose_x_kernel<<<4608, 256>>>(x, xt);
    build_weights_kernel<<<144, 256>>>(cw, ow, bst, obst);
    offset_mma_kernel<<<1152, 256, OSM_TOT>>>(xt, obst, ob, pidx, pw2);
    fused_mma_kernel<<<1152, 512, SM_TOT>>>(xt, pidx, pw2, bst, cb, out);
}

// round 15
// speedup vs baseline: 1.5017x; 1.1346x over previous
#include <cuda_runtime.h>
#include <cuda_bf16.h>
#include <cstdint>

#define BB 8
#define CC 64
#define OO 64
#define HH 96
#define WW 96
#define HW (HH*WW)
#define K2 9
#define NOFF 18
#define WP 100              // padded width/height
#define XTB (WP*WP*CC)

typedef unsigned long long ull;
typedef unsigned short ushort_t;

#define SW128(off) ((off) ^ (((off) >> 3) & 0x70))

__device__ __forceinline__ uint32_t smem_u32(const void* p) {
    uint32_t a;
    asm("{ .reg .u64 t; cvta.to.shared.u64 t, %1; cvt.u32.u64 %0, t; }" : "=r"(a) : "l"(p));
    return a;
}

#define LDSM_X4(r0, r1, r2, r3, addr) \
    asm volatile("ldmatrix.sync.aligned.m8n8.x4.shared.b16 {%0,%1,%2,%3}, [%4];" \
                 : "=r"(r0), "=r"(r1), "=r"(r2), "=r"(r3) : "r"(addr))

#define MMA16816(ac, a0, a1, a2, a3, b0, b1) \
    asm volatile("mma.sync.aligned.m16n8k16.row.col.f32.bf16.bf16.f32 " \
                 "{%0,%1,%2,%3}, {%4,%5,%6,%7}, {%8,%9}, {%0,%1,%2,%3};" \
                 : "+f"((ac)[0]), "+f"((ac)[1]), "+f"((ac)[2]), "+f"((ac)[3]) \
                 : "r"(a0), "r"(a1), "r"(a2), "r"(a3), "r"(b0), "r"(b1))

#define CP_ASYNC16(dst, src) \
    asm volatile("cp.async.cg.shared.global [%0], [%1], 16;" :: "r"(dst), "l"(src))
#define CP_COMMIT() asm volatile("cp.async.commit_group;")
#define CP_WAIT0()  asm volatile("cp.async.wait_group 0;")

#define BF16_SPLIT(sx, sy, hp, lp) do { \
    asm("cvt.rn.bf16x2.f32 %0, %1, %2;" : "=r"(hp) : "f"(sy), "f"(sx)); \
    float _hx = __uint_as_float((hp) << 16); \
    float _hy = __uint_as_float((hp) & 0xffff0000u); \
    asm("cvt.rn.bf16x2.f32 %0, %1, %2;" : "=r"(lp) : "f"((sy) - _hy), "f"((sx) - _hx)); \
} while (0)

// ---------------- scratch -----------------------------------------------------
__device__ float   g_xt[BB * XTB];             // padded NHWC x (zero border)
__device__ int     g_pidx[BB * K2 * HW];       // base idx (0 => zero corner if far)
__device__ float2  g_pw2[BB * K2 * HW];        // raw fractions (wy, wx)
__device__ ushort_t g_bst[K2 * 2 * 4096];      // conv_w bf16 [tap][hi/lo], SW128
__device__ ushort_t g_obst[K2 * 2 * 2048];     // offset_w bf16 [tap][hi/lo][32n][64c], SW128

// ---------------- transpose NCHW -> padded NHWC --------------------------------
__global__ void transpose_x_kernel(const float* __restrict__ x, float* __restrict__ xt) {
    __shared__ float tile[32][33];
    int blk = blockIdx.x;
    int pt = blk % 288, ct = (blk / 288) & 1, b = blk / 576;
    int lx = threadIdx.x & 31, ly = threadIdx.x >> 5;
    int p0 = pt * 32, c0 = ct * 32;
    int h = p0 / WW, w0 = p0 - h * WW;
    const float* xb = x + (size_t)(b * CC + c0) * HW + p0;
#pragma unroll
    for (int i = 0; i < 4; i++) {
        int cc = ly + 8 * i;
        tile[cc][lx] = xb[(size_t)cc * HW + lx];
    }
    __syncthreads();
    float* xo = xt + (size_t)b * XTB + ((size_t)(h + 2) * WP + (w0 + 2)) * CC + c0;
#pragma unroll
    for (int i = 0; i < 4; i++) {
        int pp = ly + 8 * i;
        xo[(size_t)pp * CC + lx] = tile[lx][pp];
    }
}

// ---------------- weight prep (both B matrices pre-swizzled) --------------------
__global__ void build_weights_kernel(const float* __restrict__ cw,
                                     const float* __restrict__ ow,
                                     ushort_t* __restrict__ bst,
                                     ushort_t* __restrict__ obst) {
    int idx = blockIdx.x * 256 + threadIdx.x;
    if (idx < K2 * OO * CC) {        // conv_w -> [tap][hi/lo][64o][64c]
        int k = idx / (OO * CC);
        int r = idx % (OO * CC);
        int o = r / CC;
        int c = r % CC;
        float v = cw[(size_t)(o * CC + c) * K2 + k];
        __nv_bfloat16 h = __float2bfloat16(v);
        __nv_bfloat16 l = __float2bfloat16(v - __bfloat162float(h));
        uint32_t sw = SW128((uint32_t)(o * 128 + c * 2)) >> 1;
        bst[(k * 2 + 0) * 4096 + sw] = *(ushort_t*)&h;
        bst[(k * 2 + 1) * 4096 + sw] = *(ushort_t*)&l;
    }
    if (idx < K2 * 32 * CC) {        // offset_w -> [tap][hi/lo][32n pad][64c]
        int k = idx / (32 * CC);
        int r = idx % (32 * CC);
        int n = r / CC;
        int c = r % CC;
        float v = (n < NOFF) ? ow[(size_t)(n * CC + c) * K2 + k] : 0.f;
        __nv_bfloat16 h = __float2bfloat16(v);
        __nv_bfloat16 l = __float2bfloat16(v - __bfloat162float(h));
        uint32_t sw = SW128((uint32_t)(n * 128 + c * 2)) >> 1;
        obst[(k * 2 + 0) * 2048 + sw] = *(ushort_t*)&h;
        obst[(k * 2 + 1) * 2048 + sw] = *(ushort_t*)&l;
    }
}

// ---------------- offset conv as HMMA (2-pass split) + position precompute ------
// 256 thr, tile 64 px x 32 out. smem: A 2buf x 16KB = 32KB; B hi-only 2buf x 4KB.
#define OSM_B   32768
#define OSM_TOT 40960

__global__ void __launch_bounds__(256, 4)
offset_mma_kernel(const float* __restrict__ xt, const ushort_t* __restrict__ obst,
                  const float* __restrict__ ob,
                  int* __restrict__ pidx, float2* __restrict__ pw2)
{
    extern __shared__ char smc[];
    uint32_t sbase = smem_u32(smc);
    int tid = threadIdx.x, wid = tid >> 5, lane = tid & 31;
    int b  = blockIdx.x / 144;
    int p0 = (blockIdx.x % 144) * 64;

    const float* xt_b = xt + (size_t)b * XTB;
    int c2 = 2 * lane;
    int mt = wid & 3;      // m16 tile
    int ng = wid >> 2;     // n group: 2 n8-tiles

    float acc[2][4];
#pragma unroll
    for (int i = 0; i < 2; i++)
#pragma unroll
        for (int j = 0; j < 4; j++) acc[i][j] = 0.f;

    int lr = lane & 7;
    uint32_t la0 = (uint32_t)((mt * 16 + lr + ((lane >> 3) & 1) * 8) * 128 + (lane >> 4) * 16);
    uint32_t lb0 = (uint32_t)((ng * 16 + lr + (lane >> 4) * 8) * 128 + ((lane >> 3) & 1) * 16);

    auto stageB = [&](int k, int buf) {
        // hi split only (2-pass)
        const char* src = (const char*)(obst) + (size_t)(k * 2) * 4096;
        uint32_t dst = sbase + OSM_B + (uint32_t)buf * 4096;
        CP_ASYNC16(dst + (uint32_t)tid * 16, src + (size_t)tid * 16);
        CP_COMMIT();
    };
    auto fill = [&](int k, int buf) {
        int dyk = k / 3, dxk = k % 3;
        char* Ab = smc + buf * 16384;
#pragma unroll
        for (int j = 0; j < 8; j++) {
            int px = wid + 8 * j;
            int p = p0 + px;
            int h = p / WW, w = p - h * WW;
            const float* base = xt_b + ((size_t)(h + dyk + 1) * WP + (w + dxk + 1)) * CC + c2;
            float2 g = *(const float2*)base;
            uint32_t hp, lp;
            BF16_SPLIT(g.x, g.y, hp, lp);
            uint32_t sw = SW128((uint32_t)(px * 128 + lane * 4));
            *(uint32_t*)(Ab + sw)        = hp;
            *(uint32_t*)(Ab + 8192 + sw) = lp;
        }
    };

    stageB(0, 0);
    fill(0, 0);
    CP_WAIT0();
    __syncthreads();

    for (int k = 0; k < 9; k++) {
        int buf = k & 1;
        if (k < 8) stageB(k + 1, buf ^ 1);

        uint32_t Abase = sbase + (uint32_t)buf * 16384;
        uint32_t Bbase = sbase + OSM_B + (uint32_t)buf * 4096;
#pragma unroll
        for (int ks = 0; ks < 4; ks++) {
            uint32_t la = SW128(la0 + ks * 32);
            uint32_t lb = SW128(lb0 + ks * 32);
            uint32_t ah0, ah1, ah2, ah3, al0, al1, al2, al3;
            LDSM_X4(ah0, ah1, ah2, ah3, Abase + la);
            LDSM_X4(al0, al1, al2, al3, Abase + la + 8192);
            uint32_t bh[4];
            LDSM_X4(bh[0], bh[1], bh[2], bh[3], Bbase + lb);
            MMA16816(acc[0], ah0, ah1, ah2, ah3, bh[0], bh[1]);
            MMA16816(acc[1], ah0, ah1, ah2, ah3, bh[2], bh[3]);
            MMA16816(acc[0], al0, al1, al2, al3, bh[0], bh[1]);
            MMA16816(acc[1], al0, al1, al2, al3, bh[2], bh[3]);
        }

        if (k < 8) {
            fill(k + 1, buf ^ 1);
            CP_WAIT0();
        }
        __syncthreads();
    }

    // ---- epilogue: offsets -> positions ----
    int px0 = p0 + mt * 16 + (lane >> 2);
#pragma unroll
    for (int nt = 0; nt < 2; nt++) {
        int n0 = ng * 16 + nt * 8 + 2 * (lane & 3);
        int t = n0 >> 1;
        if (t < 9) {
            float bdy = ob[n0], bdx = ob[n0 + 1];
            int tdy = t / 3 - 1, tdx = t % 3 - 1;
#pragma unroll
            for (int half = 0; half < 2; half++) {
                int p = px0 + 8 * half;
                float dy = acc[nt][2 * half]     + bdy;
                float dx = acc[nt][2 * half + 1] + bdx;
                int h = p / WW, w = p - h * WW;
                float py = (float)(h + tdy) + dy;
                float qx = (float)(w + tdx) + dx;
                float fy = floorf(py), fx = floorf(qx);
                int y0 = (int)fy, x0i = (int)fx;
                float wy = py - fy, wx = qx - fx;
                bool far = (y0 < -2) | (y0 > 96) | (x0i < -2) | (x0i > 96);
                int idx = far ? 0 : ((y0 + 2) * WP + (x0i + 2)) * CC;
                size_t gp = ((size_t)(b * 9 + t)) * HW + p;
                pidx[gp] = idx;
                pw2[gp]  = make_float2(wy, wx);
            }
        }
    }
}

// ---------------- fused: 128-px tile, m32n16 warp tile, 512 thr, 2 CTAs/SM ------
// smem: A 2buf x (hi 16384 + lo 16384) = 65536
//       B at 65536: 2buf x (hi 8192 + lo 8192) = 32768
//       sIdx at 98304 (1152 int), sFrac at 102912 (1152 float2)
#define SM_B    65536
#define SM_IDX  98304
#define SM_FR   102912
#define SM_TOT  112128

__global__ void __launch_bounds__(512, 2)
fused_mma_kernel(const float* __restrict__ xt, const int* __restrict__ pidx,
                 const float2* __restrict__ pw2, const ushort_t* __restrict__ bst,
                 const float* __restrict__ cb, float* __restrict__ out)
{
    extern __shared__ char smc[];
    uint32_t sbase = smem_u32(smc);
    int tid = threadIdx.x, wid = tid >> 5, lane = tid & 31;
    int b  = blockIdx.x / 72;
    int p0 = (blockIdx.x % 72) * 128;

    const float* xt_b = xt + (size_t)b * XTB;
    int c2 = 2 * lane;
    int*    sIdx = (int*)(smc + SM_IDX);
    float2* sFr  = (float2*)(smc + SM_FR);

    int mg = wid & 3;       // m32 group (32 px)
    int nq = wid >> 2;      // n quarter: 2 n8-tiles

    float acc[2][2][4];     // [m16 tile][n8 tile][frag]
#pragma unroll
    for (int m = 0; m < 2; m++)
#pragma unroll
        for (int i = 0; i < 2; i++)
#pragma unroll
            for (int j = 0; j < 4; j++) acc[m][i][j] = 0.f;

    int lr = lane & 7;
    uint32_t la0 = (uint32_t)((mg * 32 + lr + ((lane >> 3) & 1) * 8) * 128 + (lane >> 4) * 16);
    uint32_t lb0 = (uint32_t)((lr + (lane >> 4) * 8) * 128 + ((lane >> 3) & 1) * 16)
                 + (uint32_t)(nq * 2048);

    auto stageB = [&](int k, int buf) {
        const char* src = (const char*)(bst) + (size_t)k * 16384;
        uint32_t dst = sbase + SM_B + (uint32_t)buf * 16384;
#pragma unroll
        for (int i = 0; i < 2; i++) {
            int e = tid + 512 * i;
            CP_ASYNC16(dst + (uint32_t)e * 16, src + (size_t)e * 16);
        }
        CP_COMMIT();
    };
    auto fill = [&](int k, int buf) {
        const int*    si = sIdx + (k << 7);
        const float2* sf = sFr  + (k << 7);
        char* Ab = smc + buf * 32768;
#pragma unroll
        for (int j = 0; j < 8; j++) {
            int px = wid + 16 * j;
            int idx = si[px];
            float2 fr = sf[px];
            const float* base = xt_b + idx + c2;
            float2 g00 = *(const float2*)(base);
            float2 g01 = *(const float2*)(base + CC);
            float2 g10 = *(const float2*)(base + WP * CC);
            float2 g11 = *(const float2*)(base + WP * CC + CC);
            float wy = fr.x, wx = fr.y;
            float w00 = (1.f - wy) * (1.f - wx);
            float w01 = (1.f - wy) * wx;
            float w10 = wy * (1.f - wx);
            float w11 = wy * wx;
            float sx = g00.x*w00 + g01.x*w01 + g10.x*w10 + g11.x*w11;
            float sy = g00.y*w00 + g01.y*w01 + g10.y*w10 + g11.y*w11;
            uint32_t hp, lp;
            BF16_SPLIT(sx, sy, hp, lp);
            uint32_t sw = SW128((uint32_t)(px * 128 + lane * 4));
            *(uint32_t*)(Ab + sw)         = hp;
            *(uint32_t*)(Ab + 16384 + sw) = lp;
        }
    };

    // prologue: idx/frac (1152), stage B0, fill A0
    {
        size_t gb = (size_t)(b * 9) * HW + p0;
        for (int i = tid; i < 1152; i += 512) {
            int t = i >> 7, px = i & 127;
            size_t g = gb + (size_t)t * HW + px;
            sIdx[i] = pidx[g];
            sFr[i]  = pw2[g];
        }
    }
    stageB(0, 0);
    __syncthreads();
    fill(0, 0);
    CP_WAIT0();
    __syncthreads();

    for (int k = 0; k < 9; k++) {
        int buf = k & 1;
        if (k < 8) stageB(k + 1, buf ^ 1);

        uint32_t Abase = sbase + (uint32_t)buf * 32768;
        uint32_t Bbase = sbase + SM_B + (uint32_t)buf * 16384;
#pragma unroll
        for (int ks = 0; ks < 4; ks++) {
            uint32_t lb = SW128(lb0 + ks * 32);
            uint32_t bh[4], bl[4];
            LDSM_X4(bh[0], bh[1], bh[2], bh[3], Bbase + lb);
            LDSM_X4(bl[0], bl[1], bl[2], bl[3], Bbase + 8192 + lb);
#pragma unroll
            for (int mt = 0; mt < 2; mt++) {
                uint32_t la = SW128(la0 + (uint32_t)(mt * 2048) + ks * 32);
                uint32_t ah0, ah1, ah2, ah3, al0, al1, al2, al3;
                LDSM_X4(ah0, ah1, ah2, ah3, Abase + la);
                LDSM_X4(al0, al1, al2, al3, Abase + la + 16384);
                MMA16816(acc[mt][0], ah0, ah1, ah2, ah3, bh[0], bh[1]);
                MMA16816(acc[mt][1], ah0, ah1, ah2, ah3, bh[2], bh[3]);
                MMA16816(acc[mt][0], al0, al1, al2, al3, bh[0], bh[1]);
                MMA16816(acc[mt][1], al0, al1, al2, al3, bh[2], bh[3]);
                MMA16816(acc[mt][0], ah0, ah1, ah2, ah3, bl[0], bl[1]);
                MMA16816(acc[mt][1], ah0, ah1, ah2, ah3, bl[2], bl[3]);
            }
        }

        if (k < 8) {
            fill(k + 1, buf ^ 1);
            CP_WAIT0();
        }
        __syncthreads();
    }

    // epilogue
    int ob0 = 2 * (lane & 3);
    float* outb = out + (size_t)b * OO * HW;
#pragma unroll
    for (int mt = 0; mt < 2; mt++) {
        int px0 = p0 + mg * 32 + mt * 16 + (lane >> 2);
#pragma unroll
        for (int nt = 0; nt < 2; nt++) {
            int o = (nq * 2 + nt) * 8 + ob0;
            float b0 = cb[o], b1 = cb[o + 1];
            outb[(size_t)o * HW + px0]           = acc[mt][nt][0] + b0;
            outb[(size_t)(o + 1) * HW + px0]     = acc[mt][nt][1] + b1;
            outb[(size_t)o * HW + px0 + 8]       = acc[mt][nt][2] + b0;
            outb[(size_t)(o + 1) * HW + px0 + 8] = acc[mt][nt][3] + b1;
        }
    }
}

// ---------------- launch ---------------------------------------------------------
extern "C" void kernel_launch(void* const* d_in, const int* in_sizes, int n_in,
                              void* d_out, int out_size) {
    const float* x  = (const float*)d_in[0];
    const float* ow = (const float*)d_in[1];
    const float* ob = (const float*)d_in[2];
    const float* cw = (const float*)d_in[3];
    const float* cb = (const float*)d_in[4];
    float* out = (float*)d_out;

    float* xt;
    int* pidx;
    float2* pw2;
    ushort_t *bst, *obst;
    cudaGetSymbolAddress((void**)&xt,   g_xt);
    cudaGetSymbolAddress((void**)&pidx, g_pidx);
    cudaGetSymbolAddress((void**)&pw2,  g_pw2);
    cudaGetSymbolAddress((void**)&bst,  g_bst);
    cudaGetSymbolAddress((void**)&obst, g_obst);

    cudaFuncSetAttribute(offset_mma_kernel,
                         cudaFuncAttributeMaxDynamicSharedMemorySize, OSM_TOT);
    cudaFuncSetAttribute(fused_mma_kernel,
                         cudaFuncAttributeMaxDynamicSharedMemorySize, SM_TOT);

    transpose_x_kernel<<<4608, 256>>>(x, xt);
    build_weights_kernel<<<144, 256>>>(cw, ow, bst, obst);
    offset_mma_kernel<<<1152, 256, OSM_TOT>>>(xt, obst, ob, pidx, pw2);
    fused_mma_kernel<<<576, 512, SM_TOT>>>(xt, pidx, pw2, bst, cb, out);
}